// round 15
// baseline (speedup 1.0000x reference)
#include <cuda_runtime.h>
#include <cuda_fp16.h>
#include <cstdint>
#include <cstdlib>
#include <cstring>
#include <math.h>
#include <dlfcn.h>

// Problem constants
#define BZ    2
#define SEQ   1024
#define HID   4096
#define NHEAD 32
#define HDIM  128
#define IDIM  11008
#define MROWS 2048            // B*S
#define LOG2E 1.4426950408889634f

// ===========================================================================
// Scratch (static device memory — no allocation anywhere in kernel_launch)
// ===========================================================================
__device__ __align__(16) __half g_x   [(size_t)MROWS * HID];
__device__ __align__(16) __half g_qkv [(size_t)MROWS * 3 * HID];
__device__ __align__(16) __half g_q   [(size_t)MROWS * HID];      // [b][h][s][d]
__device__ __align__(16) __half g_k   [(size_t)MROWS * HID];      // [b][h][s][d]
__device__ __align__(16) __half g_vt  [(size_t)MROWS * HID];      // [b][h][d][s]
__device__ __align__(16) __half g_attn[(size_t)MROWS * HID];      // [b][s][h][d]
__device__ __align__(16) float  g_x2  [(size_t)MROWS * HID];
__device__ __align__(16) __half g_mlp [(size_t)MROWS * IDIM];
#define WT_QKV 0
#define WT_O   ((size_t)3 * HID * HID)
#define WT_GU  (WT_O + (size_t)HID * HID)
#define WT_DN  (WT_GU + (size_t)HID * 2 * IDIM)
#define WT_TOT (WT_DN + (size_t)HID * IDIM)
__device__ __align__(16) __half g_wT[WT_TOT];

// ===========================================================================
// NVRTC-JIT tcgen05 GEMM (sm_103a), cta_group::2: 2-CTA cluster computes a
// 256x256 tile; each CTA loads its A-half (128 rows) and B-half (128 rows),
// cutting L2->SMEM traffic 33%. Per-stage sync: cluster mapa-arrive full
// barriers (count 2 on rank 0) + commit-multicast done barriers (WAR).
// ===========================================================================
static const char* TC_SRC = R"XX(
typedef unsigned int u32;
typedef unsigned long long u64;
typedef unsigned short u16;

__device__ __forceinline__ float uf(u32 u) {
    float f; asm("mov.b32 %0, %1;" : "=f"(f) : "r"(u)); return f;
}

// C[M,N] = A[M,K](f16) @ BT[N,K](f16)^T, fp32 accum in TMEM, cta_group::2.
// Cluster (2,1,1) in grid.x; pair tile = 256 rows x 256 cols; rank r owns
// rows pairBase + r*128 (local bm = blockIdx.x*128) and B rows bn + r*128.
// EPI 1: +bias[n], f16 out. EPI 2: +residual[m,n], f32 out.
// EPI 3: silu(gate)*up (interleaved per 8 cols), f16 out stride 11008.
extern "C" __global__ void __launch_bounds__(256) tc_gemm(
    const u16* __restrict__ A, const u16* __restrict__ BT,
    const float* __restrict__ E, void* Cv, int M, int N, int K, int EPI)
{
    extern __shared__ unsigned char smem[];
    u32 smb;
    asm("{ .reg .u64 t; cvta.to.shared.u64 t, %1; cvt.u32.u64 %0, t; }" : "=r"(smb) : "l"(smem));
    const int tid = threadIdx.x;
    const int bm = blockIdx.x * 128;     // this CTA's 128 A rows (local)
    const int bn = blockIdx.y * 256;
    const int NS = K >> 6;
    u32 rank;
    asm("mov.u32 %0, %%cluster_ctarank;" : "=r"(rank));

    const u32 TMP = smb;
    const u32 F0 = smb + 8, F1 = smb + 16;     // full (count 2, used on rank 0)
    const u32 D0 = smb + 24, D1 = smb + 32;    // done (count 1, multicast)
    const u32 A0 = smb + 1024;
    const u32 B0 = A0 + 16384;
    const u32 A1 = B0 + 16384;
    const u32 B1 = A1 + 16384;

    if (tid < 32) {
        asm volatile("tcgen05.alloc.cta_group::2.sync.aligned.shared::cta.b32 [%0], %1;"
                     :: "r"(TMP), "r"(256) : "memory");
        asm volatile("tcgen05.relinquish_alloc_permit.cta_group::2.sync.aligned;");
    }
    if (tid == 0) {
        asm volatile("mbarrier.init.shared.b64 [%0], 2;" :: "r"(F0) : "memory");
        asm volatile("mbarrier.init.shared.b64 [%0], 2;" :: "r"(F1) : "memory");
        asm volatile("mbarrier.init.shared.b64 [%0], 1;" :: "r"(D0) : "memory");
        asm volatile("mbarrier.init.shared.b64 [%0], 1;" :: "r"(D1) : "memory");
    }
    __syncthreads();
    asm volatile("barrier.cluster.arrive.aligned;" ::: "memory");
    asm volatile("barrier.cluster.wait.aligned;" ::: "memory");

    u32 tmem;
    asm volatile("ld.shared.b32 %0, [%1];" : "=r"(tmem) : "r"(TMP));

    const u16* Ap = A + (u64)bm * K;
    const u16* Bp = BT + (u64)(bn + rank * 128) * K;

    u32 el = 0;
    if (tid < 32)
        asm volatile("{\n .reg .pred p;\n elect.sync _|p, 0xFFFFFFFF;\n selp.b32 %0, 1, 0, p;\n}"
                     : "=r"(el));

    // issue stage s loads: A half + B half, 4 chunks each per thread
    #define ISSUE(s) do {                                                        \
        const int k0_ = (s) << 6;                                                \
        const u32 as_ = ((s) & 1) ? A1 : A0;                                     \
        const u32 bs_ = ((s) & 1) ? B1 : B0;                                     \
        for (int j = 0; j < 4; j++) {                                            \
            int c = tid + j * 256;                                               \
            int row = c >> 3, col = c & 7;                                       \
            u32 off = (u32)(row * 128 + col * 16); off ^= (off >> 3) & 0x70;     \
            asm volatile("cp.async.cg.shared.global [%0], [%1], 16;"             \
                         :: "r"(as_ + off), "l"(Ap + (u64)row * K + k0_ + col * 8)); \
        }                                                                        \
        for (int j = 0; j < 4; j++) {                                            \
            int c = tid + j * 256;                                               \
            int row = c >> 3, col = c & 7;                                       \
            u32 off = (u32)(row * 128 + col * 16); off ^= (off >> 3) & 0x70;     \
            asm volatile("cp.async.cg.shared.global [%0], [%1], 16;"             \
                         :: "r"(bs_ + off), "l"(Bp + (u64)row * K + k0_ + col * 8)); \
        }                                                                        \
        asm volatile("cp.async.commit_group;" ::: "memory");                     \
    } while (0)

    #define MWAIT(addr, ph) do {                                                 \
        u32 done_;                                                               \
        asm volatile("{\n .reg .pred p;\n"                                       \
            " mbarrier.try_wait.parity.acquire.cta.shared::cta.b64 p, [%1], %2;\n" \
            " selp.b32 %0, 1, 0, p;\n}" : "=r"(done_) : "r"(addr), "r"((u32)(ph)) : "memory"); \
        while (!done_) {                                                         \
            asm volatile("{\n .reg .pred p;\n"                                   \
                " mbarrier.try_wait.parity.acquire.cta.shared::cta.b64 p, [%1], %2;\n" \
                " selp.b32 %0, 1, 0, p;\n}" : "=r"(done_) : "r"(addr), "r"((u32)(ph)) : "memory"); \
        }                                                                        \
    } while (0)

    ISSUE(0);

    int fp[2] = {0, 0};
    int dp[2] = {0, 0};
    const u16 msk = 3;

    for (int i = 0; i < NS; i++) {
        asm volatile("cp.async.wait_group 0;" ::: "memory");
        __syncthreads();
        asm volatile("fence.proxy.async.shared::cta;" ::: "memory");
        const int buf = i & 1;
        const u32 FULL = buf ? F1 : F0;
        const u32 DONE = buf ? D1 : D0;
        if (tid == 0) {
            asm volatile("{\n .reg .b32 ra;\n"
                " mapa.shared::cluster.u32 ra, %0, 0;\n"
                " mbarrier.arrive.shared::cluster.b64 _, [ra];\n}"
                :: "r"(FULL) : "memory");
        }
        if (rank == 0 && el) {
            MWAIT(FULL, fp[buf]);
            const u64 DB = (2ULL << 61) | (1ULL << 46) | (64ULL << 32) | (1ULL << 16);
            u64 ad = DB | (u64)(((buf ? A1 : A0) >> 4) & 0x3FFF);
            u64 bd = DB | (u64)(((buf ? B1 : B0) >> 4) & 0x3FFF);
            #pragma unroll
            for (int k = 0; k < 4; k++) {
                u32 en = (i > 0 || k > 0) ? 1u : 0u;
                asm volatile("{\n .reg .pred p;\n setp.ne.u32 p, %5, 0;\n"
                    " tcgen05.mma.cta_group::2.kind::f16 [%0], %1, %2, %3, "
                    "{%4, %4, %4, %4, %4, %4, %4, %4}, p;\n}"
                    :: "r"(tmem), "l"(ad + 2 * k), "l"(bd + 2 * k),
                       "r"(0x10400010u), "r"(0u), "r"(en) : "memory");
            }
            asm volatile("tcgen05.commit.cta_group::2.mbarrier::arrive::one"
                ".shared::cluster.multicast::cluster.b64 [%0], %1;"
                :: "r"(DONE), "h"(msk) : "memory");
        }
        fp[buf] ^= 1;
        if (i + 1 < NS) {
            const int b2 = (i + 1) & 1;
            if (i >= 1) {
                MWAIT(b2 ? D1 : D0, dp[b2]);
                dp[b2] ^= 1;
            }
            ISSUE(i + 1);
        }
    }
    {
        const int lb = (NS - 1) & 1;
        MWAIT(lb ? D1 : D0, dp[lb]);
    }
    asm volatile("tcgen05.fence::after_thread_sync;" ::: "memory");

    // ---- epilogue: warp w -> rows (w&3)*32+lane of THIS CTA, cols (w>>2)*128
    const int w = tid >> 5, lane = tid & 31;
    const int grow = bm + (w & 3) * 32 + lane;
    const int cbase = (w >> 2) * 128;
    for (int ch = 0; ch < 4; ch++) {
        u32 r[32];
        asm volatile("tcgen05.ld.sync.aligned.32x32b.x32.b32 "
            "{%0,%1,%2,%3,%4,%5,%6,%7,%8,%9,%10,%11,%12,%13,%14,%15,"
            "%16,%17,%18,%19,%20,%21,%22,%23,%24,%25,%26,%27,%28,%29,%30,%31}, [%32];"
            : "=r"(r[0]),  "=r"(r[1]),  "=r"(r[2]),  "=r"(r[3]),
              "=r"(r[4]),  "=r"(r[5]),  "=r"(r[6]),  "=r"(r[7]),
              "=r"(r[8]),  "=r"(r[9]),  "=r"(r[10]), "=r"(r[11]),
              "=r"(r[12]), "=r"(r[13]), "=r"(r[14]), "=r"(r[15]),
              "=r"(r[16]), "=r"(r[17]), "=r"(r[18]), "=r"(r[19]),
              "=r"(r[20]), "=r"(r[21]), "=r"(r[22]), "=r"(r[23]),
              "=r"(r[24]), "=r"(r[25]), "=r"(r[26]), "=r"(r[27]),
              "=r"(r[28]), "=r"(r[29]), "=r"(r[30]), "=r"(r[31])
            : "r"(tmem + (u32)(cbase + ch * 32)));
        asm volatile("tcgen05.wait::ld.sync.aligned;" ::: "memory");
        const int gcol = bn + cbase + ch * 32;
        if (EPI == 1) {
            u16* C = (u16*)Cv;
            const u64 ob = (u64)grow * (u64)N + (u64)gcol;
            #pragma unroll
            for (int q = 0; q < 4; q++) {
                u32 pk[4];
                #pragma unroll
                for (int d = 0; d < 4; d++) {
                    const int j = q * 8 + d * 2;
                    float v0 = uf(r[j]) + E[gcol + j];
                    float v1 = uf(r[j + 1]) + E[gcol + j + 1];
                    u16 h0, h1;
                    asm("cvt.rn.f16.f32 %0, %1;" : "=h"(h0) : "f"(v0));
                    asm("cvt.rn.f16.f32 %0, %1;" : "=h"(h1) : "f"(v1));
                    pk[d] = (u32)h0 | ((u32)h1 << 16);
                }
                asm volatile("st.global.v4.b32 [%0], {%1,%2,%3,%4};"
                             :: "l"(C + ob + q * 8), "r"(pk[0]), "r"(pk[1]), "r"(pk[2]), "r"(pk[3]));
            }
        } else if (EPI == 2) {
            float* C = (float*)Cv;
            const u64 ob = (u64)grow * (u64)N + (u64)gcol;
            #pragma unroll
            for (int q = 0; q < 8; q++) {
                float e0, e1, e2, e3;
                asm("ld.global.v4.f32 {%0,%1,%2,%3}, [%4];"
                    : "=f"(e0), "=f"(e1), "=f"(e2), "=f"(e3) : "l"(E + ob + q * 4));
                float v0 = uf(r[q * 4 + 0]) + e0;
                float v1 = uf(r[q * 4 + 1]) + e1;
                float v2 = uf(r[q * 4 + 2]) + e2;
                float v3 = uf(r[q * 4 + 3]) + e3;
                asm volatile("st.global.v4.f32 [%0], {%1,%2,%3,%4};"
                             :: "l"(C + ob + q * 4), "f"(v0), "f"(v1), "f"(v2), "f"(v3));
            }
        } else {
            u16* C = (u16*)Cv;
            const int l0 = (gcol >> 4) * 8;
            const u64 ob = (u64)grow * 11008ULL + (u64)l0;
            u32 pk[8];
            #pragma unroll
            for (int gi = 0; gi < 16; gi++) {
                const int j = (gi < 8) ? gi : (gi + 8);
                float gv = uf(r[j]);
                float up = uf(r[j + 8]);
                float t;
                asm("ex2.approx.f32 %0, %1;" : "=f"(t) : "f"(-1.4426950408889634f * gv));
                float v = gv / (1.0f + t) * up;
                u16 h;
                asm("cvt.rn.f16.f32 %0, %1;" : "=h"(h) : "f"(v));
                if (gi & 1) pk[gi >> 1] |= ((u32)h << 16);
                else        pk[gi >> 1] = (u32)h;
            }
            asm volatile("st.global.v4.b32 [%0], {%1,%2,%3,%4};"
                         :: "l"(C + ob), "r"(pk[0]), "r"(pk[1]), "r"(pk[2]), "r"(pk[3]));
            asm volatile("st.global.v4.b32 [%0], {%1,%2,%3,%4};"
                         :: "l"(C + ob + 8), "r"(pk[4]), "r"(pk[5]), "r"(pk[6]), "r"(pk[7]));
        }
    }
    asm volatile("tcgen05.fence::before_thread_sync;" ::: "memory");
    __syncthreads();
    if (tid < 32)
        asm volatile("tcgen05.dealloc.cta_group::2.sync.aligned.b32 %0, %1;"
                     :: "r"(tmem), "r"(256));
    asm volatile("barrier.cluster.arrive.aligned;" ::: "memory");
    asm volatile("barrier.cluster.wait.aligned;" ::: "memory");
}
)XX";

typedef int nvrtcResult_;
typedef void* nvrtcProg_;
typedef nvrtcResult_ (*PFN_nvrtcCreateProgram)(nvrtcProg_*, const char*, const char*,
    int, const char* const*, const char* const*);
typedef nvrtcResult_ (*PFN_nvrtcCompileProgram)(nvrtcProg_, int, const char* const*);
typedef nvrtcResult_ (*PFN_nvrtcGetCUBINSize)(nvrtcProg_, size_t*);
typedef nvrtcResult_ (*PFN_nvrtcGetCUBIN)(nvrtcProg_, char*);

#define TC_SMEM 66560

struct TcJit {
    bool ok = false;
    cudaKernel_t kern = nullptr;

    static void launch_raw(cudaKernel_t k, const void* A, const void* BT, const void* E,
                           void* C, int M, int N, int K, int EPI, cudaStream_t s) {
        cudaLaunchConfig_t cfg = {};
        cfg.gridDim = dim3((unsigned)(M / 128), (unsigned)(N / 256), 1);   // M fastest
        cfg.blockDim = dim3(256, 1, 1);
        cfg.dynamicSmemBytes = TC_SMEM;
        cfg.stream = s;
        cudaLaunchAttribute attrs[1];
        attrs[0].id = cudaLaunchAttributeClusterDimension;
        attrs[0].val.clusterDim.x = 2;
        attrs[0].val.clusterDim.y = 1;
        attrs[0].val.clusterDim.z = 1;
        cfg.attrs = attrs;
        cfg.numAttrs = 1;
        void* a = (void*)A; void* b = (void*)BT; void* e = (void*)E; void* c = C;
        void* params[8] = {&a, &b, &e, &c, &M, &N, &K, &EPI};
        cudaLaunchKernelExC(&cfg, (const void*)k, params);
    }

    TcJit() {
        void* hn = dlopen("libnvrtc.so.13", RTLD_NOW | RTLD_GLOBAL);
        if (!hn) hn = dlopen("libnvrtc.so", RTLD_NOW | RTLD_GLOBAL);
        if (!hn) hn = dlopen("libnvrtc.so.12", RTLD_NOW | RTLD_GLOBAL);
        if (!hn) return;
        auto pCreate  = (PFN_nvrtcCreateProgram)dlsym(hn, "nvrtcCreateProgram");
        auto pCompile = (PFN_nvrtcCompileProgram)dlsym(hn, "nvrtcCompileProgram");
        auto pSize    = (PFN_nvrtcGetCUBINSize)dlsym(hn, "nvrtcGetCUBINSize");
        auto pGet     = (PFN_nvrtcGetCUBIN)dlsym(hn, "nvrtcGetCUBIN");
        if (!pCreate || !pCompile || !pSize || !pGet) return;
        nvrtcProg_ prog = nullptr;
        if (pCreate(&prog, TC_SRC, "tc.cu", 0, nullptr, nullptr) != 0) return;
        const char* opts[] = {"--gpu-architecture=sm_103a", "--std=c++17"};
        if (pCompile(prog, 2, opts) != 0) return;
        size_t sz = 0;
        if (pSize(prog, &sz) != 0 || sz == 0) return;
        char* cubin = (char*)malloc(sz);
        if (!cubin || pGet(prog, cubin) != 0) return;

        cudaLibrary_t lib = nullptr;
        if (cudaLibraryLoadData(&lib, cubin, nullptr, nullptr, 0, nullptr, nullptr, 0)
            != cudaSuccess) return;
        if (cudaLibraryGetKernel(&kern, lib, "tc_gemm") != cudaSuccess || !kern) return;
        if (cudaFuncSetAttribute((const void*)kern,
                                 cudaFuncAttributeMaxDynamicSharedMemorySize,
                                 TC_SMEM) != cudaSuccess) return;

        // ---- numeric self-test: M=256 (one full cluster pair), N=256, K=128 ----
        const int M = 256, N = 256, K = 128;
        __half *dA = nullptr, *dBT = nullptr, *dC = nullptr;
        float* dE = nullptr;
        if (cudaMalloc(&dA, (size_t)M * K * 2)) return;
        if (cudaMalloc(&dBT, (size_t)N * K * 2)) return;
        if (cudaMalloc(&dC, (size_t)M * N * 2)) return;
        if (cudaMalloc(&dE, (size_t)N * 4)) return;
        __half* hA = (__half*)malloc((size_t)M * K * 2);
        __half* hB = (__half*)malloc((size_t)N * K * 2);
        float*  hE = (float*)malloc((size_t)N * 4);
        __half* hC = (__half*)malloc((size_t)M * N * 2);
        for (int i = 0; i < M * K; i++)
            hA[i] = __float2half_rn(0.1f * (float)((i * 7 + 3) % 13 - 6));
        for (int i = 0; i < N * K; i++)
            hB[i] = __float2half_rn(0.05f * (float)((i * 5 + 11) % 17 - 8));
        for (int i = 0; i < N; i++) hE[i] = 0.01f * (float)i;
        cudaMemcpy(dA, hA, (size_t)M * K * 2, cudaMemcpyHostToDevice);
        cudaMemcpy(dBT, hB, (size_t)N * K * 2, cudaMemcpyHostToDevice);
        cudaMemcpy(dE, hE, (size_t)N * 4, cudaMemcpyHostToDevice);
        cudaMemset(dC, 0, (size_t)M * N * 2);
        launch_raw(kern, dA, dBT, dE, dC, M, N, K, 1, 0);
        if (cudaDeviceSynchronize() != cudaSuccess) { cudaGetLastError(); goto cleanup; }
        if (cudaGetLastError() != cudaSuccess) goto cleanup;
        cudaMemcpy(hC, dC, (size_t)M * N * 2, cudaMemcpyDeviceToHost);
        {
            bool good = true;
            for (int r = 0; r < M && good; r += 7) {
                for (int n = 0; n < N && good; n += 11) {
                    float ref = hE[n];
                    for (int k = 0; k < K; k++)
                        ref += __half2float(hA[r * K + k]) * __half2float(hB[n * K + k]);
                    float got = __half2float(hC[r * N + n]);
                    if (fabsf(got - ref) > 0.05f + 0.02f * fabsf(ref)) good = false;
                }
            }
            if (good) ok = true;
        }
    cleanup:
        cudaFree(dA); cudaFree(dBT); cudaFree(dC); cudaFree(dE);
        free(hA); free(hB); free(hE); free(hC);
    }
};
static TcJit g_tc;

static inline void tc_gemm_launch(const __half* A, const __half* BT, const float* E,
                                  void* C, int M, int N, int K, int EPI) {
    TcJit::launch_raw(g_tc.kern, A, BT, E, C, M, N, K, EPI, 0);
}

// Host-side stream/event resources (created before harness mem baseline).
struct AsyncRes {
    cudaStream_t s1;
    cudaEvent_t evRoot, evQ, evW;
    AsyncRes() {
        cudaStreamCreateWithFlags(&s1, cudaStreamNonBlocking);
        cudaEventCreateWithFlags(&evRoot, cudaEventDisableTiming);
        cudaEventCreateWithFlags(&evQ, cudaEventDisableTiming);
        cudaEventCreateWithFlags(&evW, cudaEventDisableTiming);
    }
};
static AsyncRes g_ar;

__device__ __forceinline__ uint32_t smem_u32(const void* p) {
    uint32_t a;
    asm("{ .reg .u64 t; cvta.to.shared.u64 t, %1; cvt.u32.u64 %0, t; }" : "=r"(a) : "l"(p));
    return a;
}
__device__ __forceinline__ void cp16(uint32_t dst, const void* src) {
    asm volatile("cp.async.cg.shared.global [%0], [%1], 16;" :: "r"(dst), "l"(src));
}
#define CP_COMMIT() asm volatile("cp.async.commit_group;" ::: "memory")
#define CP_WAIT1()  asm volatile("cp.async.wait_group 1;" ::: "memory")
#define CP_WAIT0()  asm volatile("cp.async.wait_group 0;" ::: "memory")

__device__ __forceinline__ void mma_f16_k16(float* c, const uint32_t* a, const uint32_t* b) {
    asm volatile("mma.sync.aligned.m16n8k16.row.col.f32.f16.f16.f32 "
                 "{%0,%1,%2,%3}, {%4,%5,%6,%7}, {%8,%9}, {%0,%1,%2,%3};"
                 : "+f"(c[0]), "+f"(c[1]), "+f"(c[2]), "+f"(c[3])
                 : "r"(a[0]), "r"(a[1]), "r"(a[2]), "r"(a[3]), "r"(b[0]), "r"(b[1]));
}
#define LDMX4(r0, r1, r2, r3, addr) \
    asm volatile("ldmatrix.sync.aligned.m8n8.x4.shared.b16 {%0,%1,%2,%3}, [%4];" \
                 : "=r"(r0), "=r"(r1), "=r"(r2), "=r"(r3) : "r"(addr))

__device__ __forceinline__ uint32_t ex2h2(float a, float b) {
    __half2 h = __floats2half2_rn(a, b);
    uint32_t u = *(uint32_t*)&h, r;
    asm("ex2.approx.f16x2 %0, %1;" : "=r"(r) : "r"(u));
    return r;
}

// ===========================================================================
// Weight transpose + fp16: src fp32 [K][N] -> dst fp16 [N][K]
// MODE 0: direct; MODE 1: gate/up interleave
// ===========================================================================
template <int MODE>
__global__ __launch_bounds__(256) void transpose_h_kernel(const float* __restrict__ src,
                                                          __half* __restrict__ dst,
                                                          int K, int N) {
    __shared__ float tile[32][33];
    const int bx = blockIdx.x * 32;
    const int by = blockIdx.y * 32;
    const int tx = threadIdx.x & 31, ty = threadIdx.x >> 5;
#pragma unroll
    for (int j = 0; j < 32; j += 8)
        tile[ty + j][tx] = src[(size_t)(by + ty + j) * N + bx + tx];
    __syncthreads();
#pragma unroll
    for (int j = 0; j < 32; j += 8) {
        int n = bx + ty + j;
        int m;
        if (MODE == 1)
            m = (n < IDIM) ? ((n >> 3) * 16 + (n & 7))
                           : (((n - IDIM) >> 3) * 16 + 8 + (n & 7));
        else
            m = n;
        dst[(size_t)m * K + by + tx] = __float2half_rn(tile[tx][ty + j]);
    }
}

// ===========================================================================
// FALLBACK fp16 mma.sync GEMM
// ===========================================================================
#define GBM 128
#define GBK 32
#define HPITCH 40
#define SA_STG (GBM * HPITCH)
#define NSTG 3
#define GEMM_SMEM_N8 (NSTG * (SA_STG + 256 * HPITCH) * 2)
#define GEMM_SMEM_N4 (NSTG * (SA_STG + 128 * HPITCH) * 2)

template <int EPI, int NTL>
__global__ __launch_bounds__(256, (NTL == 4) ? 2 : 1)
void mma_gemm_kernel(const __half* __restrict__ A,
                     const __half* __restrict__ BT,
                     const float* __restrict__ E,
                     void* __restrict__ Cv,
                     int M, int N, int K) {
    constexpr int BN = NTL * 32;
    constexpr int SB_STG = BN * HPITCH;
    constexpr int STG_HW = SA_STG + SB_STG;
    extern __shared__ __half smem[];

    const int tid = threadIdx.x;
    const int bm = blockIdx.y * GBM;
    const int bn = blockIdx.x * BN;
    const int w = tid >> 5, lane = tid & 31;
    const int wm = (w & 1) * 64;
    const int wn = (w >> 1) * (NTL * 8);

    const int quad = lane >> 3;
    const int qr = (quad & 1) * 8 + (lane & 7);
    const int qk = (quad >> 1) * 8;
    const uint32_t lmoff = (uint32_t)(qr * HPITCH + qk) * 2;

    const __half* Ap = A + (size_t)bm * K;
    const __half* Bp = BT + (size_t)bn * K;
    const int NS = K / GBK;

    const int crow = tid >> 2;
    const int ccol = tid & 3;
    const uint32_t sbase = smem_u32(smem);

    float acc[4][NTL][4];
#pragma unroll
    for (int mt = 0; mt < 4; mt++)
#pragma unroll
        for (int nt = 0; nt < NTL; nt++)
#pragma unroll
            for (int i = 0; i < 4; i++) acc[mt][nt][i] = 0.f;

    auto issue = [&](int s) {
        const int buf = s % NSTG;
        const int k0 = s * GBK;
        const uint32_t sa = sbase + buf * STG_HW * 2;
        const uint32_t sb = sa + SA_STG * 2;
#pragma unroll
        for (int j = 0; j < 2; j++) {
            const int row = crow + j * 64;
            cp16(sa + row * 80 + ccol * 16, Ap + (size_t)row * K + k0 + ccol * 8);
        }
#pragma unroll
        for (int j = 0; j < BN / 64; j++) {
            const int row = crow + j * 64;
            cp16(sb + row * 80 + ccol * 16, Bp + (size_t)row * K + k0 + ccol * 8);
        }
    };

    issue(0); CP_COMMIT();
    if (NS > 1) { issue(1); CP_COMMIT(); }

    for (int s = 0; s < NS; s++) {
        if (s + 1 < NS) CP_WAIT1(); else CP_WAIT0();
        __syncthreads();
        if (s + 2 < NS) { issue(s + 2); CP_COMMIT(); }

        const int buf = s % NSTG;
        const uint32_t abase = sbase + buf * STG_HW * 2 + lmoff;
        const uint32_t bbase = abase + SA_STG * 2;

#pragma unroll
        for (int ks = 0; ks < 2; ks++) {
            uint32_t afr[4][4], bfr[NTL][2];
            const uint32_t koff = ks * 32;
#pragma unroll
            for (int mt = 0; mt < 4; mt++) {
                const uint32_t ad = abase + (wm + mt * 16) * 80 + koff;
                LDMX4(afr[mt][0], afr[mt][1], afr[mt][2], afr[mt][3], ad);
            }
#pragma unroll
            for (int np = 0; np < NTL / 2; np++) {
                const uint32_t bd = bbase + (wn + np * 16) * 80 + koff;
                LDMX4(bfr[2 * np][0], bfr[2 * np + 1][0],
                      bfr[2 * np][1], bfr[2 * np + 1][1], bd);
            }
#pragma unroll
            for (int mt = 0; mt < 4; mt++)
#pragma unroll
                for (int nt = 0; nt < NTL; nt++)
                    mma_f16_k16(acc[mt][nt], afr[mt], bfr[nt]);
        }
        __syncthreads();
    }

    const int g = lane >> 2, t = lane & 3;
    if (EPI == 1) {
        __half* C = (__half*)Cv;
#pragma unroll
        for (int mt = 0; mt < 4; mt++) {
            const int row0 = bm + wm + mt * 16 + g;
#pragma unroll
            for (int nt = 0; nt < NTL; nt++) {
                const int col = bn + wn + nt * 8 + 2 * t;
                const float2 e = *(const float2*)&E[col];
                *(__half2*)&C[(size_t)row0 * N + col] =
                    __floats2half2_rn(acc[mt][nt][0] + e.x, acc[mt][nt][1] + e.y);
                *(__half2*)&C[(size_t)(row0 + 8) * N + col] =
                    __floats2half2_rn(acc[mt][nt][2] + e.x, acc[mt][nt][3] + e.y);
            }
        }
    } else if (EPI == 2) {
        float* C = (float*)Cv;
#pragma unroll
        for (int mt = 0; mt < 4; mt++) {
            const int row0 = bm + wm + mt * 16 + g;
#pragma unroll
            for (int nt = 0; nt < NTL; nt++) {
                const int col = bn + wn + nt * 8 + 2 * t;
                const float2 e0 = *(const float2*)&E[(size_t)row0 * N + col];
                const float2 e1 = *(const float2*)&E[(size_t)(row0 + 8) * N + col];
                *(float2*)&C[(size_t)row0 * N + col] =
                    make_float2(acc[mt][nt][0] + e0.x, acc[mt][nt][1] + e0.y);
                *(float2*)&C[(size_t)(row0 + 8) * N + col] =
                    make_float2(acc[mt][nt][2] + e1.x, acc[mt][nt][3] + e1.y);
            }
        }
    } else {
        __half* C = (__half*)Cv;
#pragma unroll
        for (int mt = 0; mt < 4; mt++) {
            const int row0 = bm + wm + mt * 16 + g;
#pragma unroll
            for (int nt = 0; nt < NTL; nt += 2) {
                const int pcol = bn + wn + nt * 8;
                const int ocol = (pcol >> 4) * 8 + 2 * t;
                float v[4];
#pragma unroll
                for (int i = 0; i < 4; i++) {
                    const float gv = acc[mt][nt][i];
                    v[i] = gv / (1.f + __expf(-gv)) * acc[mt][nt + 1][i];
                }
                *(__half2*)&C[(size_t)row0 * IDIM + ocol] = __floats2half2_rn(v[0], v[1]);
                *(__half2*)&C[(size_t)(row0 + 8) * IDIM + ocol] = __floats2half2_rn(v[2], v[3]);
            }
        }
    }
}

// ===========================================================================
// RMSNorm: fp32 in, fp16 out
// ===========================================================================
__global__ __launch_bounds__(256) void rmsnorm_kernel(const float* __restrict__ x,
                                                      const float* __restrict__ w,
                                                      __half* __restrict__ out) {
    const size_t base = (size_t)blockIdx.x * HID;
    const float4* xr = (const float4*)(x + base);
    const float4* w4 = (const float4*)w;
    __half2* orow = (__half2*)(out + base);

    float4 v[4];
    float ss = 0.f;
#pragma unroll
    for (int it = 0; it < 4; it++) {
        v[it] = xr[threadIdx.x + 256 * it];
        ss += v[it].x * v[it].x + v[it].y * v[it].y + v[it].z * v[it].z + v[it].w * v[it].w;
    }
#pragma unroll
    for (int o = 16; o; o >>= 1) ss += __shfl_xor_sync(0xffffffffu, ss, o);

    __shared__ float warpsum[8];
    __shared__ float s_inv;
    const int lane = threadIdx.x & 31, wid = threadIdx.x >> 5;
    if (lane == 0) warpsum[wid] = ss;
    __syncthreads();
    if (threadIdx.x == 0) {
        float tsum = 0.f;
#pragma unroll
        for (int i = 0; i < 8; i++) tsum += warpsum[i];
        s_inv = rsqrtf(tsum * (1.0f / (float)HID) + 1e-6f);
    }
    __syncthreads();
    const float inv = s_inv;
#pragma unroll
    for (int it = 0; it < 4; it++) {
        const int idx = threadIdx.x + 256 * it;
        float4 wv = w4[idx];
        orow[idx * 2 + 0] = __floats2half2_rn(v[it].x * inv * wv.x, v[it].y * inv * wv.y);
        orow[idx * 2 + 1] = __floats2half2_rn(v[it].z * inv * wv.z, v[it].w * inv * wv.w);
    }
}

// ===========================================================================
// RoPE + split (fp16 in): q pre-scaled by log2e/sqrt(d), v transposed
// ===========================================================================
__global__ void rope_split_kernel(const __half* __restrict__ qkv,
                                  const int* __restrict__ positions,
                                  __half* __restrict__ q, __half* __restrict__ k,
                                  __half* __restrict__ vt) {
    const int row = blockIdx.x;
    const int h = blockIdx.y;
    const int d = threadIdx.x;   // 0..63
    const int b = row >> 10, s = row & (SEQ - 1);
    const float pos = (float)positions[s];
    const float freq = powf(10000.0f, -(float)d * (1.0f / 64.0f));
    float sn, cs;
    sincosf(pos * freq, &sn, &cs);
    const float scale = 0.08838834764831845f * LOG2E;

    const __half* base = qkv + (size_t)row * (3 * HID) + h * HDIM;
    const float q1 = __half2float(base[d]), q2 = __half2float(base[d + 64]);
    const float k1 = __half2float(base[HID + d]), k2 = __half2float(base[HID + d + 64]);

    const size_t hb = (size_t)(b * NHEAD + h);
    __half* qp = q + (hb * SEQ + s) * HDIM;
    __half* kp = k + (hb * SEQ + s) * HDIM;
    qp[d]      = __float2half_rn((q1 * cs - q2 * sn) * scale);
    qp[d + 64] = __float2half_rn((q2 * cs + q1 * sn) * scale);
    kp[d]      = __float2half_rn(k1 * cs - k2 * sn);
    kp[d + 64] = __float2half_rn(k2 * cs + k1 * sn);
    vt[(hb * HDIM + d) * SEQ + s]      = base[2 * HID + d];
    vt[(hb * HDIM + d + 64) * SEQ + s] = base[2 * HID + d + 64];
}

// ===========================================================================
// fp16 tensor-core flash attention (causal), log2-domain softmax.
// Heavy q-tiles scheduled first (qt reversed) to cut causal tail imbalance.
// ===========================================================================
#define QPW 68
#define VPW 36
#define AQ_OFF 0
#define AK_OFF (128 * 136)
#define AV_OFF (AK_OFF + 2 * 64 * 136)
#define ATTN_SMEM ((AV_OFF + 2 * 128 * 72) * 2)

__global__ __launch_bounds__(256, 1) void attn_mma_kernel(const __half* __restrict__ q,
                                                          const __half* __restrict__ k,
                                                          const __half* __restrict__ vt,
                                                          __half* __restrict__ attn) {
    extern __shared__ __half asm_[];
    const uint32_t sbase = smem_u32(asm_);
    const int tid = threadIdx.x;
    const int qt = gridDim.x - 1 - blockIdx.x;   // heavy tiles first
    const int h = blockIdx.y, b = blockIdx.z;
    const int w = tid >> 5, lane = tid & 31;
    const int g = lane >> 2, t = lane & 3;

    const size_t hb = (size_t)(b * NHEAD + h);
    const __half* qg = q + (hb * SEQ + qt * 128) * HDIM;
    const __half* kg = k + hb * SEQ * HDIM;
    const __half* vg = vt + hb * HDIM * SEQ;

    {
#pragma unroll
        for (int i = 0; i < 8; i++) {
            const int id = tid + i * 256;
            const int r = id >> 4, c = id & 15;
            cp16(sbase + AQ_OFF * 2 + r * 272 + c * 16, qg + (size_t)r * HDIM + c * 8);
        }
    }
    CP_COMMIT(); CP_WAIT0();
    __syncthreads();

    uint32_t afrQ[8][4];
    {
        const uint32_t* Qw = (const uint32_t*)(asm_ + AQ_OFF);
        const int r0 = 16 * w + g;
#pragma unroll
        for (int ks = 0; ks < 8; ks++) {
            afrQ[ks][0] = Qw[r0 * QPW + ks * 8 + t];
            afrQ[ks][1] = Qw[(r0 + 8) * QPW + ks * 8 + t];
            afrQ[ks][2] = Qw[r0 * QPW + ks * 8 + t + 4];
            afrQ[ks][3] = Qw[(r0 + 8) * QPW + ks * 8 + t + 4];
        }
    }
    __syncthreads();

    float O[16][4];
#pragma unroll
    for (int nt = 0; nt < 16; nt++)
#pragma unroll
        for (int i = 0; i < 4; i++) O[nt][i] = 0.f;
    float m0 = -1e30f, m1 = -1e30f, l0 = 0.f, l1 = 0.f;

    const int NT = 2 * qt + 2;

    auto issue = [&](int j) {
        const uint32_t kb = sbase + AK_OFF * 2 + (j & 1) * (64 * 136 * 2);
        const uint32_t vb = sbase + AV_OFF * 2 + (j & 1) * (128 * 72 * 2);
#pragma unroll
        for (int i = 0; i < 4; i++) {
            const int id = tid + i * 256;
            const int r = id >> 4, c = id & 15;
            cp16(kb + r * 272 + c * 16, kg + (size_t)(j * 64 + r) * HDIM + c * 8);
            const int d = id >> 3, c2 = id & 7;
            cp16(vb + d * 144 + c2 * 16, vg + (size_t)d * SEQ + j * 64 + c2 * 8);
        }
    };

    issue(0); CP_COMMIT();
    if (NT > 1) { issue(1); CP_COMMIT(); }

    const int rowg0 = qt * 128 + 16 * w + g;

    for (int j = 0; j < NT; j++) {
        if (j + 1 < NT) CP_WAIT1(); else CP_WAIT0();
        __syncthreads();

        const uint32_t* Kw = (const uint32_t*)(asm_ + AK_OFF + (j & 1) * 64 * 136);
        const uint32_t* Vw = (const uint32_t*)(asm_ + AV_OFF + (j & 1) * 128 * 72);

        float S[8][4];
#pragma unroll
        for (int nt = 0; nt < 8; nt++)
#pragma unroll
            for (int i = 0; i < 4; i++) S[nt][i] = 0.f;
#pragma unroll
        for (int ks = 0; ks < 8; ks++) {
            uint32_t bf[8][2];
#pragma unroll
            for (int nt = 0; nt < 8; nt++) {
                bf[nt][0] = Kw[(nt * 8 + g) * QPW + ks * 8 + t];
                bf[nt][1] = Kw[(nt * 8 + g) * QPW + ks * 8 + t + 4];
            }
#pragma unroll
            for (int nt = 0; nt < 8; nt++)
                mma_f16_k16(S[nt], afrQ[ks], bf[nt]);
        }

        if (j >= 2 * qt) {
#pragma unroll
            for (int nt = 0; nt < 8; nt++) {
                const int c0 = j * 64 + nt * 8 + 2 * t;
                if (c0 > rowg0)     S[nt][0] = -1e30f;
                if (c0 + 1 > rowg0) S[nt][1] = -1e30f;
                if (c0 > rowg0 + 8)     S[nt][2] = -1e30f;
                if (c0 + 1 > rowg0 + 8) S[nt][3] = -1e30f;
            }
        }

        float mx0 = -1e30f, mx1 = -1e30f;
#pragma unroll
        for (int nt = 0; nt < 8; nt++) {
            mx0 = fmaxf(mx0, fmaxf(S[nt][0], S[nt][1]));
            mx1 = fmaxf(mx1, fmaxf(S[nt][2], S[nt][3]));
        }
        mx0 = fmaxf(mx0, __shfl_xor_sync(0xffffffffu, mx0, 1));
        mx0 = fmaxf(mx0, __shfl_xor_sync(0xffffffffu, mx0, 2));
        mx1 = fmaxf(mx1, __shfl_xor_sync(0xffffffffu, mx1, 1));
        mx1 = fmaxf(mx1, __shfl_xor_sync(0xffffffffu, mx1, 2));
        const float mn0 = fmaxf(m0, mx0), mn1 = fmaxf(m1, mx1);
        const float cr0 = exp2f(m0 - mn0), cr1 = exp2f(m1 - mn1);

        uint32_t pf[4][4];
        float ps0 = 0.f, ps1 = 0.f;
#pragma unroll
        for (int nt = 0; nt < 8; nt++) {
            const uint32_t h01 = ex2h2(S[nt][0] - mn0, S[nt][1] - mn0);
            const uint32_t h23 = ex2h2(S[nt][2] - mn1, S[nt][3] - mn1);
            pf[nt >> 1][(nt & 1) ? 2 : 0] = h01;
            pf[nt >> 1][(nt & 1) ? 3 : 1] = h23;
            const float2 f01 = __half22float2(*(const __half2*)&h01);
            const float2 f23 = __half22float2(*(const __half2*)&h23);
            ps0 += f01.x + f01.y;
            ps1 += f23.x + f23.y;
        }
        ps0 += __shfl_xor_sync(0xffffffffu, ps0, 1);
        ps0 += __shfl_xor_sync(0xffffffffu, ps0, 2);
        ps1 += __shfl_xor_sync(0xffffffffu, ps1, 1);
        ps1 += __shfl_xor_sync(0xffffffffu, ps1, 2);
        l0 = l0 * cr0 + ps0;
        l1 = l1 * cr1 + ps1;
        m0 = mn0; m1 = mn1;
#pragma unroll
        for (int nt = 0; nt < 16; nt++) {
            O[nt][0] *= cr0; O[nt][1] *= cr0;
            O[nt][2] *= cr1; O[nt][3] *= cr1;
        }

#pragma unroll
        for (int kk = 0; kk < 4; kk++) {
#pragma unroll
            for (int nt = 0; nt < 16; nt++) {
                uint32_t bv[2];
                bv[0] = Vw[(nt * 8 + g) * VPW + kk * 8 + t];
                bv[1] = Vw[(nt * 8 + g) * VPW + kk * 8 + t + 4];
                mma_f16_k16(O[nt], pf[kk], bv);
            }
        }

        __syncthreads();
        if (j + 2 < NT) { issue(j + 2); CP_COMMIT(); }
    }

    const float inv0 = 1.0f / l0, inv1 = 1.0f / l1;
    __half* orow0 = attn + ((size_t)(b * SEQ + qt * 128 + 16 * w + g)) * HID + h * HDIM;
    __half* orow1 = orow0 + 8 * HID;
#pragma unroll
    for (int nt = 0; nt < 16; nt++) {
        const int c = nt * 8 + 2 * t;
        *(__half2*)&orow0[c] = __floats2half2_rn(O[nt][0] * inv0, O[nt][1] * inv0);
        *(__half2*)&orow1[c] = __floats2half2_rn(O[nt][2] * inv1, O[nt][3] * inv1);
    }
}

// ===========================================================================
// Launch
// ===========================================================================
extern "C" void kernel_launch(void* const* d_in, const int* in_sizes, int n_in,
                              void* d_out, int out_size) {
    const int*   positions = (const int*)  d_in[0];
    const float* hidden    = (const float*)d_in[1];
    const float* ln1       = (const float*)d_in[2];
    const float* ln2       = (const float*)d_in[3];
    const float* w_qkv     = (const float*)d_in[4];
    const float* b_qkv     = (const float*)d_in[5];
    const float* w_o       = (const float*)d_in[6];
    const float* w_gu      = (const float*)d_in[7];
    const float* w_down    = (const float*)d_in[8];
    float* out = (float*)d_out;

    void* p;
    cudaGetSymbolAddress(&p, g_x);    __half* x    = (__half*)p;
    cudaGetSymbolAddress(&p, g_qkv);  __half* qkv  = (__half*)p;
    cudaGetSymbolAddress(&p, g_q);    __half* qh   = (__half*)p;
    cudaGetSymbolAddress(&p, g_k);    __half* kh   = (__half*)p;
    cudaGetSymbolAddress(&p, g_vt);   __half* vth  = (__half*)p;
    cudaGetSymbolAddress(&p, g_attn); __half* attn = (__half*)p;
    cudaGetSymbolAddress(&p, g_x2);   float*  x2   = (float*)p;
    cudaGetSymbolAddress(&p, g_mlp);  __half* mlp  = (__half*)p;
    cudaGetSymbolAddress(&p, g_wT);   __half* wT   = (__half*)p;
    __half* qkvT = wT + WT_QKV;
    __half* oT   = wT + WT_O;
    __half* guT  = wT + WT_GU;
    __half* dnT  = wT + WT_DN;

    cudaFuncSetAttribute(attn_mma_kernel, cudaFuncAttributeMaxDynamicSharedMemorySize, ATTN_SMEM);
    cudaFuncSetAttribute((const void*)mma_gemm_kernel<1, 8>,
                         cudaFuncAttributeMaxDynamicSharedMemorySize, GEMM_SMEM_N8);
    cudaFuncSetAttribute((const void*)mma_gemm_kernel<3, 8>,
                         cudaFuncAttributeMaxDynamicSharedMemorySize, GEMM_SMEM_N8);
    cudaFuncSetAttribute((const void*)mma_gemm_kernel<2, 4>,
                         cudaFuncAttributeMaxDynamicSharedMemorySize, GEMM_SMEM_N4);

    // ---- fork: weight transposes on s1 ----
    cudaEventRecord(g_ar.evRoot, 0);
    cudaStreamWaitEvent(g_ar.s1, g_ar.evRoot, 0);
    transpose_h_kernel<0><<<dim3((3 * HID) / 32, HID / 32), 256, 0, g_ar.s1>>>(
        w_qkv, qkvT, HID, 3 * HID);
    cudaEventRecord(g_ar.evQ, g_ar.s1);
    transpose_h_kernel<0><<<dim3(HID / 32, HID / 32), 256, 0, g_ar.s1>>>(w_o, oT, HID, HID);
    transpose_h_kernel<1><<<dim3((2 * IDIM) / 32, HID / 32), 256, 0, g_ar.s1>>>(
        w_gu, guT, HID, 2 * IDIM);
    transpose_h_kernel<0><<<dim3(HID / 32, IDIM / 32), 256, 0, g_ar.s1>>>(w_down, dnT, IDIM, HID);
    cudaEventRecord(g_ar.evW, g_ar.s1);

    // ---- main chain on stream 0 ----
    rmsnorm_kernel<<<MROWS, 256>>>(hidden, ln1, x);
    cudaStreamWaitEvent(0, g_ar.evQ, 0);
    // qkv = x @ w_qkv + b_qkv
    if (g_tc.ok)
        tc_gemm_launch(x, qkvT, b_qkv, qkv, MROWS, 3 * HID, HID, 1);
    else
        mma_gemm_kernel<1, 8><<<dim3((3 * HID) / 256, MROWS / GBM), 256, GEMM_SMEM_N8>>>(
            x, qkvT, b_qkv, qkv, MROWS, 3 * HID, HID);
    rope_split_kernel<<<dim3(MROWS, NHEAD), 64>>>(qkv, positions, qh, kh, vth);
    attn_mma_kernel<<<dim3(SEQ / 128, NHEAD, BZ), 256, ATTN_SMEM>>>(qh, kh, vth, attn);
    cudaStreamWaitEvent(0, g_ar.evW, 0);
    // x2 = hidden + attn @ w_o
    if (g_tc.ok)
        tc_gemm_launch(attn, oT, hidden, x2, MROWS, HID, HID, 2);
    else
        mma_gemm_kernel<2, 4><<<dim3(HID / 128, MROWS / GBM), 256, GEMM_SMEM_N4>>>(
            attn, oT, hidden, x2, MROWS, HID, HID);
    rmsnorm_kernel<<<MROWS, 256>>>(x2, ln2, x);
    // mlp = silu(gate)*up fused
    if (g_tc.ok)
        tc_gemm_launch(x, guT, nullptr, mlp, MROWS, 2 * IDIM, HID, 3);
    else
        mma_gemm_kernel<3, 8><<<dim3((2 * IDIM) / 256, MROWS / GBM), 256, GEMM_SMEM_N8>>>(
            x, guT, nullptr, mlp, MROWS, 2 * IDIM, HID);
    // out = x2 + mlp @ w_down
    if (g_tc.ok)
        tc_gemm_launch(mlp, dnT, x2, out, MROWS, HID, IDIM, 2);
    else
        mma_gemm_kernel<2, 4><<<dim3(HID / 128, MROWS / GBM), 256, GEMM_SMEM_N4>>>(
            mlp, dnT, x2, out, MROWS, HID, IDIM);
}

// round 16
// speedup vs baseline: 1.2348x; 1.2348x over previous
#include <cuda_runtime.h>
#include <cuda_fp16.h>
#include <cstdint>
#include <cstdlib>
#include <cstring>
#include <math.h>
#include <dlfcn.h>

// Problem constants
#define BZ    2
#define SEQ   1024
#define HID   4096
#define NHEAD 32
#define HDIM  128
#define IDIM  11008
#define MROWS 2048            // B*S
#define LOG2E 1.4426950408889634f

// ===========================================================================
// Scratch (static device memory — no allocation anywhere in kernel_launch)
// ===========================================================================
__device__ __align__(16) __half g_x   [(size_t)MROWS * HID];
__device__ __align__(16) __half g_qkv [(size_t)MROWS * 3 * HID];
__device__ __align__(16) __half g_q   [(size_t)MROWS * HID];      // [b][h][s][d]
__device__ __align__(16) __half g_k   [(size_t)MROWS * HID];      // [b][h][s][d]
__device__ __align__(16) __half g_vt  [(size_t)MROWS * HID];      // [b][h][d][s]
__device__ __align__(16) __half g_attn[(size_t)MROWS * HID];      // [b][s][h][d]
__device__ __align__(16) float  g_x2  [(size_t)MROWS * HID];
__device__ __align__(16) __half g_mlp [(size_t)MROWS * IDIM];
#define WT_QKV 0
#define WT_O   ((size_t)3 * HID * HID)
#define WT_GU  (WT_O + (size_t)HID * HID)
#define WT_DN  (WT_GU + (size_t)HID * 2 * IDIM)
#define WT_TOT (WT_DN + (size_t)HID * IDIM)
__device__ __align__(16) __half g_wT[WT_TOT];

// ===========================================================================
// NVRTC-JIT tcgen05 GEMM (sm_103a), cta_group::2, 3-STAGE pipeline:
// 2-CTA cluster computes a 256x256 tile; each CTA loads its A-half and B-half
// (32 KB/stage). Three buffers + cp.async.wait_group 1 keep two load stages
// in flight so loads overlap MMA. FULL[3]/DONE[3] barriers with per-buffer
// phases; WAR wait on DONE[(i-1)%3] before reusing its buffer for stage i+2.
// ===========================================================================
static const char* TC_SRC = R"XX(
typedef unsigned int u32;
typedef unsigned long long u64;
typedef unsigned short u16;

__device__ __forceinline__ float uf(u32 u) {
    float f; asm("mov.b32 %0, %1;" : "=f"(f) : "r"(u)); return f;
}

// C[M,N] = A[M,K](f16) @ BT[N,K](f16)^T, fp32 accum in TMEM, cta_group::2.
// Cluster (2,1,1) in grid.x; rank r owns A rows blockIdx.x*128 and B rows
// bn + r*128. EPI 1: +bias[n], f16 out. EPI 2: +residual, f32 out.
// EPI 3: silu(gate)*up (interleaved per 8 cols), f16 out stride 11008.
extern "C" __global__ void __launch_bounds__(256) tc_gemm(
    const u16* __restrict__ A, const u16* __restrict__ BT,
    const float* __restrict__ E, void* Cv, int M, int N, int K, int EPI)
{
    extern __shared__ unsigned char smem[];
    u32 smb;
    asm("{ .reg .u64 t; cvta.to.shared.u64 t, %1; cvt.u32.u64 %0, t; }" : "=r"(smb) : "l"(smem));
    const int tid = threadIdx.x;
    const int bm = blockIdx.x * 128;
    const int bn = blockIdx.y * 256;
    const int NS = K >> 6;
    u32 rank;
    asm("mov.u32 %0, %%cluster_ctarank;" : "=r"(rank));

    const u32 TMP = smb;
    // FULL[s] = smb+8+8s (count 2), DONE[s] = smb+32+8s (count 1)
    const u32 FULLB = smb + 8;
    const u32 DONEB = smb + 32;
    const u32 DATA0 = smb + 1024;   // stage s: A at DATA0+s*32768, B at +16384

    if (tid < 32) {
        asm volatile("tcgen05.alloc.cta_group::2.sync.aligned.shared::cta.b32 [%0], %1;"
                     :: "r"(TMP), "r"(256) : "memory");
        asm volatile("tcgen05.relinquish_alloc_permit.cta_group::2.sync.aligned;");
    }
    if (tid == 0) {
        #pragma unroll
        for (int s = 0; s < 3; s++) {
            asm volatile("mbarrier.init.shared.b64 [%0], 2;" :: "r"(FULLB + 8 * s) : "memory");
            asm volatile("mbarrier.init.shared.b64 [%0], 1;" :: "r"(DONEB + 8 * s) : "memory");
        }
    }
    __syncthreads();
    asm volatile("barrier.cluster.arrive.aligned;" ::: "memory");
    asm volatile("barrier.cluster.wait.aligned;" ::: "memory");

    u32 tmem;
    asm volatile("ld.shared.b32 %0, [%1];" : "=r"(tmem) : "r"(TMP));

    const u16* Ap = A + (u64)bm * K;
    const u16* Bp = BT + (u64)(bn + rank * 128) * K;

    u32 el = 0;
    if (tid < 32)
        asm volatile("{\n .reg .pred p;\n elect.sync _|p, 0xFFFFFFFF;\n selp.b32 %0, 1, 0, p;\n}"
                     : "=r"(el));

    #define ISSUE(s) do {                                                        \
        const int k0_ = (s) << 6;                                                \
        const u32 as_ = DATA0 + (u32)((s) % 3) * 32768u;                         \
        const u32 bs_ = as_ + 16384u;                                            \
        for (int j = 0; j < 4; j++) {                                            \
            int c = tid + j * 256;                                               \
            int row = c >> 3, col = c & 7;                                       \
            u32 off = (u32)(row * 128 + col * 16); off ^= (off >> 3) & 0x70;     \
            asm volatile("cp.async.cg.shared.global [%0], [%1], 16;"             \
                         :: "r"(as_ + off), "l"(Ap + (u64)row * K + k0_ + col * 8)); \
        }                                                                        \
        for (int j = 0; j < 4; j++) {                                            \
            int c = tid + j * 256;                                               \
            int row = c >> 3, col = c & 7;                                       \
            u32 off = (u32)(row * 128 + col * 16); off ^= (off >> 3) & 0x70;     \
            asm volatile("cp.async.cg.shared.global [%0], [%1], 16;"             \
                         :: "r"(bs_ + off), "l"(Bp + (u64)row * K + k0_ + col * 8)); \
        }                                                                        \
        asm volatile("cp.async.commit_group;" ::: "memory");                     \
    } while (0)

    #define MWAIT(addr, ph) do {                                                 \
        u32 done_;                                                               \
        asm volatile("{\n .reg .pred p;\n"                                       \
            " mbarrier.try_wait.parity.acquire.cta.shared::cta.b64 p, [%1], %2;\n" \
            " selp.b32 %0, 1, 0, p;\n}" : "=r"(done_) : "r"(addr), "r"((u32)(ph)) : "memory"); \
        while (!done_) {                                                         \
            asm volatile("{\n .reg .pred p;\n"                                   \
                " mbarrier.try_wait.parity.acquire.cta.shared::cta.b64 p, [%1], %2;\n" \
                " selp.b32 %0, 1, 0, p;\n}" : "=r"(done_) : "r"(addr), "r"((u32)(ph)) : "memory"); \
        }                                                                        \
    } while (0)

    ISSUE(0);
    if (NS > 1) ISSUE(1);

    int fp[3] = {0, 0, 0};
    int dp[3] = {0, 0, 0};
    const u16 msk = 3;

    for (int i = 0; i < NS; i++) {
        if (i + 1 < NS)
            asm volatile("cp.async.wait_group 1;" ::: "memory");
        else
            asm volatile("cp.async.wait_group 0;" ::: "memory");
        __syncthreads();
        asm volatile("fence.proxy.async.shared::cta;" ::: "memory");
        const int buf = i % 3;
        const u32 FULL = FULLB + 8 * buf;
        const u32 DONE = DONEB + 8 * buf;
        if (tid == 0) {
            asm volatile("{\n .reg .b32 ra;\n"
                " mapa.shared::cluster.u32 ra, %0, 0;\n"
                " mbarrier.arrive.shared::cluster.b64 _, [ra];\n}"
                :: "r"(FULL) : "memory");
        }
        if (rank == 0 && el) {
            MWAIT(FULL, fp[buf]);
            const u64 DB = (2ULL << 61) | (1ULL << 46) | (64ULL << 32) | (1ULL << 16);
            const u32 as_ = DATA0 + (u32)buf * 32768u;
            u64 ad = DB | (u64)((as_ >> 4) & 0x3FFF);
            u64 bd = DB | (u64)(((as_ + 16384u) >> 4) & 0x3FFF);
            #pragma unroll
            for (int k = 0; k < 4; k++) {
                u32 en = (i > 0 || k > 0) ? 1u : 0u;
                asm volatile("{\n .reg .pred p;\n setp.ne.u32 p, %5, 0;\n"
                    " tcgen05.mma.cta_group::2.kind::f16 [%0], %1, %2, %3, "
                    "{%4, %4, %4, %4, %4, %4, %4, %4}, p;\n}"
                    :: "r"(tmem), "l"(ad + 2 * k), "l"(bd + 2 * k),
                       "r"(0x10400010u), "r"(0u), "r"(en) : "memory");
            }
            asm volatile("tcgen05.commit.cta_group::2.mbarrier::arrive::one"
                ".shared::cluster.multicast::cluster.b64 [%0], %1;"
                :: "r"(DONE), "h"(msk) : "memory");
        }
        fp[buf] ^= 1;
        if (i + 2 < NS) {
            if (i >= 1) {
                const int wb = (i - 1) % 3;     // buffer that stage i+2 reuses
                MWAIT(DONEB + 8 * wb, dp[wb]);
                dp[wb] ^= 1;
            }
            ISSUE(i + 2);
        }
    }
    {
        const int lb = (NS - 1) % 3;
        MWAIT(DONEB + 8 * lb, dp[lb]);
    }
    asm volatile("tcgen05.fence::after_thread_sync;" ::: "memory");

    // ---- epilogue: warp w -> rows (w&3)*32+lane of THIS CTA, cols (w>>2)*128
    const int w = tid >> 5, lane = tid & 31;
    const int grow = bm + (w & 3) * 32 + lane;
    const int cbase = (w >> 2) * 128;
    for (int ch = 0; ch < 4; ch++) {
        u32 r[32];
        asm volatile("tcgen05.ld.sync.aligned.32x32b.x32.b32 "
            "{%0,%1,%2,%3,%4,%5,%6,%7,%8,%9,%10,%11,%12,%13,%14,%15,"
            "%16,%17,%18,%19,%20,%21,%22,%23,%24,%25,%26,%27,%28,%29,%30,%31}, [%32];"
            : "=r"(r[0]),  "=r"(r[1]),  "=r"(r[2]),  "=r"(r[3]),
              "=r"(r[4]),  "=r"(r[5]),  "=r"(r[6]),  "=r"(r[7]),
              "=r"(r[8]),  "=r"(r[9]),  "=r"(r[10]), "=r"(r[11]),
              "=r"(r[12]), "=r"(r[13]), "=r"(r[14]), "=r"(r[15]),
              "=r"(r[16]), "=r"(r[17]), "=r"(r[18]), "=r"(r[19]),
              "=r"(r[20]), "=r"(r[21]), "=r"(r[22]), "=r"(r[23]),
              "=r"(r[24]), "=r"(r[25]), "=r"(r[26]), "=r"(r[27]),
              "=r"(r[28]), "=r"(r[29]), "=r"(r[30]), "=r"(r[31])
            : "r"(tmem + (u32)(cbase + ch * 32)));
        asm volatile("tcgen05.wait::ld.sync.aligned;" ::: "memory");
        const int gcol = bn + cbase + ch * 32;
        if (EPI == 1) {
            u16* C = (u16*)Cv;
            const u64 ob = (u64)grow * (u64)N + (u64)gcol;
            #pragma unroll
            for (int q = 0; q < 4; q++) {
                u32 pk[4];
                #pragma unroll
                for (int d = 0; d < 4; d++) {
                    const int j = q * 8 + d * 2;
                    float v0 = uf(r[j]) + E[gcol + j];
                    float v1 = uf(r[j + 1]) + E[gcol + j + 1];
                    u16 h0, h1;
                    asm("cvt.rn.f16.f32 %0, %1;" : "=h"(h0) : "f"(v0));
                    asm("cvt.rn.f16.f32 %0, %1;" : "=h"(h1) : "f"(v1));
                    pk[d] = (u32)h0 | ((u32)h1 << 16);
                }
                asm volatile("st.global.v4.b32 [%0], {%1,%2,%3,%4};"
                             :: "l"(C + ob + q * 8), "r"(pk[0]), "r"(pk[1]), "r"(pk[2]), "r"(pk[3]));
            }
        } else if (EPI == 2) {
            float* C = (float*)Cv;
            const u64 ob = (u64)grow * (u64)N + (u64)gcol;
            #pragma unroll
            for (int q = 0; q < 8; q++) {
                float e0, e1, e2, e3;
                asm("ld.global.v4.f32 {%0,%1,%2,%3}, [%4];"
                    : "=f"(e0), "=f"(e1), "=f"(e2), "=f"(e3) : "l"(E + ob + q * 4));
                float v0 = uf(r[q * 4 + 0]) + e0;
                float v1 = uf(r[q * 4 + 1]) + e1;
                float v2 = uf(r[q * 4 + 2]) + e2;
                float v3 = uf(r[q * 4 + 3]) + e3;
                asm volatile("st.global.v4.f32 [%0], {%1,%2,%3,%4};"
                             :: "l"(C + ob + q * 4), "f"(v0), "f"(v1), "f"(v2), "f"(v3));
            }
        } else {
            u16* C = (u16*)Cv;
            const int l0 = (gcol >> 4) * 8;
            const u64 ob = (u64)grow * 11008ULL + (u64)l0;
            u32 pk[8];
            #pragma unroll
            for (int gi = 0; gi < 16; gi++) {
                const int j = (gi < 8) ? gi : (gi + 8);
                float gv = uf(r[j]);
                float up = uf(r[j + 8]);
                float t;
                asm("ex2.approx.f32 %0, %1;" : "=f"(t) : "f"(-1.4426950408889634f * gv));
                float v = gv / (1.0f + t) * up;
                u16 h;
                asm("cvt.rn.f16.f32 %0, %1;" : "=h"(h) : "f"(v));
                if (gi & 1) pk[gi >> 1] |= ((u32)h << 16);
                else        pk[gi >> 1] = (u32)h;
            }
            asm volatile("st.global.v4.b32 [%0], {%1,%2,%3,%4};"
                         :: "l"(C + ob), "r"(pk[0]), "r"(pk[1]), "r"(pk[2]), "r"(pk[3]));
            asm volatile("st.global.v4.b32 [%0], {%1,%2,%3,%4};"
                         :: "l"(C + ob + 8), "r"(pk[4]), "r"(pk[5]), "r"(pk[6]), "r"(pk[7]));
        }
    }
    asm volatile("tcgen05.fence::before_thread_sync;" ::: "memory");
    __syncthreads();
    if (tid < 32)
        asm volatile("tcgen05.dealloc.cta_group::2.sync.aligned.b32 %0, %1;"
                     :: "r"(tmem), "r"(256));
    asm volatile("barrier.cluster.arrive.aligned;" ::: "memory");
    asm volatile("barrier.cluster.wait.aligned;" ::: "memory");
}
)XX";

typedef int nvrtcResult_;
typedef void* nvrtcProg_;
typedef nvrtcResult_ (*PFN_nvrtcCreateProgram)(nvrtcProg_*, const char*, const char*,
    int, const char* const*, const char* const*);
typedef nvrtcResult_ (*PFN_nvrtcCompileProgram)(nvrtcProg_, int, const char* const*);
typedef nvrtcResult_ (*PFN_nvrtcGetCUBINSize)(nvrtcProg_, size_t*);
typedef nvrtcResult_ (*PFN_nvrtcGetCUBIN)(nvrtcProg_, char*);

#define TC_SMEM 99328

struct TcJit {
    bool ok = false;
    cudaKernel_t kern = nullptr;

    static void launch_raw(cudaKernel_t k, const void* A, const void* BT, const void* E,
                           void* C, int M, int N, int K, int EPI, cudaStream_t s) {
        cudaLaunchConfig_t cfg = {};
        cfg.gridDim = dim3((unsigned)(M / 128), (unsigned)(N / 256), 1);   // M fastest
        cfg.blockDim = dim3(256, 1, 1);
        cfg.dynamicSmemBytes = TC_SMEM;
        cfg.stream = s;
        cudaLaunchAttribute attrs[1];
        attrs[0].id = cudaLaunchAttributeClusterDimension;
        attrs[0].val.clusterDim.x = 2;
        attrs[0].val.clusterDim.y = 1;
        attrs[0].val.clusterDim.z = 1;
        cfg.attrs = attrs;
        cfg.numAttrs = 1;
        void* a = (void*)A; void* b = (void*)BT; void* e = (void*)E; void* c = C;
        void* params[8] = {&a, &b, &e, &c, &M, &N, &K, &EPI};
        cudaLaunchKernelExC(&cfg, (const void*)k, params);
    }

    TcJit() {
        void* hn = dlopen("libnvrtc.so.13", RTLD_NOW | RTLD_GLOBAL);
        if (!hn) hn = dlopen("libnvrtc.so", RTLD_NOW | RTLD_GLOBAL);
        if (!hn) hn = dlopen("libnvrtc.so.12", RTLD_NOW | RTLD_GLOBAL);
        if (!hn) return;
        auto pCreate  = (PFN_nvrtcCreateProgram)dlsym(hn, "nvrtcCreateProgram");
        auto pCompile = (PFN_nvrtcCompileProgram)dlsym(hn, "nvrtcCompileProgram");
        auto pSize    = (PFN_nvrtcGetCUBINSize)dlsym(hn, "nvrtcGetCUBINSize");
        auto pGet     = (PFN_nvrtcGetCUBIN)dlsym(hn, "nvrtcGetCUBIN");
        if (!pCreate || !pCompile || !pSize || !pGet) return;
        nvrtcProg_ prog = nullptr;
        if (pCreate(&prog, TC_SRC, "tc.cu", 0, nullptr, nullptr) != 0) return;
        const char* opts[] = {"--gpu-architecture=sm_103a", "--std=c++17"};
        if (pCompile(prog, 2, opts) != 0) return;
        size_t sz = 0;
        if (pSize(prog, &sz) != 0 || sz == 0) return;
        char* cubin = (char*)malloc(sz);
        if (!cubin || pGet(prog, cubin) != 0) return;

        cudaLibrary_t lib = nullptr;
        if (cudaLibraryLoadData(&lib, cubin, nullptr, nullptr, 0, nullptr, nullptr, 0)
            != cudaSuccess) return;
        if (cudaLibraryGetKernel(&kern, lib, "tc_gemm") != cudaSuccess || !kern) return;
        if (cudaFuncSetAttribute((const void*)kern,
                                 cudaFuncAttributeMaxDynamicSharedMemorySize,
                                 TC_SMEM) != cudaSuccess) return;

        // ---- numeric self-test: M=256 cluster pair, N=256, K=256 (NS=4,
        // exercises all 3 buffers + WAR path) ----
        const int M = 256, N = 256, K = 256;
        __half *dA = nullptr, *dBT = nullptr, *dC = nullptr;
        float* dE = nullptr;
        if (cudaMalloc(&dA, (size_t)M * K * 2)) return;
        if (cudaMalloc(&dBT, (size_t)N * K * 2)) return;
        if (cudaMalloc(&dC, (size_t)M * N * 2)) return;
        if (cudaMalloc(&dE, (size_t)N * 4)) return;
        __half* hA = (__half*)malloc((size_t)M * K * 2);
        __half* hB = (__half*)malloc((size_t)N * K * 2);
        float*  hE = (float*)malloc((size_t)N * 4);
        __half* hC = (__half*)malloc((size_t)M * N * 2);
        for (int i = 0; i < M * K; i++)
            hA[i] = __float2half_rn(0.1f * (float)((i * 7 + 3) % 13 - 6));
        for (int i = 0; i < N * K; i++)
            hB[i] = __float2half_rn(0.05f * (float)((i * 5 + 11) % 17 - 8));
        for (int i = 0; i < N; i++) hE[i] = 0.01f * (float)i;
        cudaMemcpy(dA, hA, (size_t)M * K * 2, cudaMemcpyHostToDevice);
        cudaMemcpy(dBT, hB, (size_t)N * K * 2, cudaMemcpyHostToDevice);
        cudaMemcpy(dE, hE, (size_t)N * 4, cudaMemcpyHostToDevice);
        cudaMemset(dC, 0, (size_t)M * N * 2);
        launch_raw(kern, dA, dBT, dE, dC, M, N, K, 1, 0);
        if (cudaDeviceSynchronize() != cudaSuccess) { cudaGetLastError(); goto cleanup; }
        if (cudaGetLastError() != cudaSuccess) goto cleanup;
        cudaMemcpy(hC, dC, (size_t)M * N * 2, cudaMemcpyDeviceToHost);
        {
            bool good = true;
            for (int r = 0; r < M && good; r += 7) {
                for (int n = 0; n < N && good; n += 11) {
                    float ref = hE[n];
                    for (int k = 0; k < K; k++)
                        ref += __half2float(hA[r * K + k]) * __half2float(hB[n * K + k]);
                    float got = __half2float(hC[r * N + n]);
                    if (fabsf(got - ref) > 0.08f + 0.02f * fabsf(ref)) good = false;
                }
            }
            if (good) ok = true;
        }
    cleanup:
        cudaFree(dA); cudaFree(dBT); cudaFree(dC); cudaFree(dE);
        free(hA); free(hB); free(hE); free(hC);
    }
};
static TcJit g_tc;

static inline void tc_gemm_launch(const __half* A, const __half* BT, const float* E,
                                  void* C, int M, int N, int K, int EPI) {
    TcJit::launch_raw(g_tc.kern, A, BT, E, C, M, N, K, EPI, 0);
}

// Host-side stream/event resources (created before harness mem baseline).
struct AsyncRes {
    cudaStream_t s1;
    cudaEvent_t evRoot, evQ, evW;
    AsyncRes() {
        cudaStreamCreateWithFlags(&s1, cudaStreamNonBlocking);
        cudaEventCreateWithFlags(&evRoot, cudaEventDisableTiming);
        cudaEventCreateWithFlags(&evQ, cudaEventDisableTiming);
        cudaEventCreateWithFlags(&evW, cudaEventDisableTiming);
    }
};
static AsyncRes g_ar;

__device__ __forceinline__ uint32_t smem_u32(const void* p) {
    uint32_t a;
    asm("{ .reg .u64 t; cvta.to.shared.u64 t, %1; cvt.u32.u64 %0, t; }" : "=r"(a) : "l"(p));
    return a;
}
__device__ __forceinline__ void cp16(uint32_t dst, const void* src) {
    asm volatile("cp.async.cg.shared.global [%0], [%1], 16;" :: "r"(dst), "l"(src));
}
#define CP_COMMIT() asm volatile("cp.async.commit_group;" ::: "memory")
#define CP_WAIT1()  asm volatile("cp.async.wait_group 1;" ::: "memory")
#define CP_WAIT0()  asm volatile("cp.async.wait_group 0;" ::: "memory")

__device__ __forceinline__ void mma_f16_k16(float* c, const uint32_t* a, const uint32_t* b) {
    asm volatile("mma.sync.aligned.m16n8k16.row.col.f32.f16.f16.f32 "
                 "{%0,%1,%2,%3}, {%4,%5,%6,%7}, {%8,%9}, {%0,%1,%2,%3};"
                 : "+f"(c[0]), "+f"(c[1]), "+f"(c[2]), "+f"(c[3])
                 : "r"(a[0]), "r"(a[1]), "r"(a[2]), "r"(a[3]), "r"(b[0]), "r"(b[1]));
}
#define LDMX4(r0, r1, r2, r3, addr) \
    asm volatile("ldmatrix.sync.aligned.m8n8.x4.shared.b16 {%0,%1,%2,%3}, [%4];" \
                 : "=r"(r0), "=r"(r1), "=r"(r2), "=r"(r3) : "r"(addr))

__device__ __forceinline__ uint32_t ex2h2(float a, float b) {
    __half2 h = __floats2half2_rn(a, b);
    uint32_t u = *(uint32_t*)&h, r;
    asm("ex2.approx.f16x2 %0, %1;" : "=r"(r) : "r"(u));
    return r;
}

// ===========================================================================
// Weight transpose + fp16: src fp32 [K][N] -> dst fp16 [N][K]
// MODE 0: direct; MODE 1: gate/up interleave
// ===========================================================================
template <int MODE>
__global__ __launch_bounds__(256) void transpose_h_kernel(const float* __restrict__ src,
                                                          __half* __restrict__ dst,
                                                          int K, int N) {
    __shared__ float tile[32][33];
    const int bx = blockIdx.x * 32;
    const int by = blockIdx.y * 32;
    const int tx = threadIdx.x & 31, ty = threadIdx.x >> 5;
#pragma unroll
    for (int j = 0; j < 32; j += 8)
        tile[ty + j][tx] = src[(size_t)(by + ty + j) * N + bx + tx];
    __syncthreads();
#pragma unroll
    for (int j = 0; j < 32; j += 8) {
        int n = bx + ty + j;
        int m;
        if (MODE == 1)
            m = (n < IDIM) ? ((n >> 3) * 16 + (n & 7))
                           : (((n - IDIM) >> 3) * 16 + 8 + (n & 7));
        else
            m = n;
        dst[(size_t)m * K + by + tx] = __float2half_rn(tile[tx][ty + j]);
    }
}

// ===========================================================================
// FALLBACK fp16 mma.sync GEMM
// ===========================================================================
#define GBM 128
#define GBK 32
#define HPITCH 40
#define SA_STG (GBM * HPITCH)
#define NSTG 3
#define GEMM_SMEM_N8 (NSTG * (SA_STG + 256 * HPITCH) * 2)
#define GEMM_SMEM_N4 (NSTG * (SA_STG + 128 * HPITCH) * 2)

template <int EPI, int NTL>
__global__ __launch_bounds__(256, (NTL == 4) ? 2 : 1)
void mma_gemm_kernel(const __half* __restrict__ A,
                     const __half* __restrict__ BT,
                     const float* __restrict__ E,
                     void* __restrict__ Cv,
                     int M, int N, int K) {
    constexpr int BN = NTL * 32;
    constexpr int SB_STG = BN * HPITCH;
    constexpr int STG_HW = SA_STG + SB_STG;
    extern __shared__ __half smem[];

    const int tid = threadIdx.x;
    const int bm = blockIdx.y * GBM;
    const int bn = blockIdx.x * BN;
    const int w = tid >> 5, lane = tid & 31;
    const int wm = (w & 1) * 64;
    const int wn = (w >> 1) * (NTL * 8);

    const int quad = lane >> 3;
    const int qr = (quad & 1) * 8 + (lane & 7);
    const int qk = (quad >> 1) * 8;
    const uint32_t lmoff = (uint32_t)(qr * HPITCH + qk) * 2;

    const __half* Ap = A + (size_t)bm * K;
    const __half* Bp = BT + (size_t)bn * K;
    const int NS = K / GBK;

    const int crow = tid >> 2;
    const int ccol = tid & 3;
    const uint32_t sbase = smem_u32(smem);

    float acc[4][NTL][4];
#pragma unroll
    for (int mt = 0; mt < 4; mt++)
#pragma unroll
        for (int nt = 0; nt < NTL; nt++)
#pragma unroll
            for (int i = 0; i < 4; i++) acc[mt][nt][i] = 0.f;

    auto issue = [&](int s) {
        const int buf = s % NSTG;
        const int k0 = s * GBK;
        const uint32_t sa = sbase + buf * STG_HW * 2;
        const uint32_t sb = sa + SA_STG * 2;
#pragma unroll
        for (int j = 0; j < 2; j++) {
            const int row = crow + j * 64;
            cp16(sa + row * 80 + ccol * 16, Ap + (size_t)row * K + k0 + ccol * 8);
        }
#pragma unroll
        for (int j = 0; j < BN / 64; j++) {
            const int row = crow + j * 64;
            cp16(sb + row * 80 + ccol * 16, Bp + (size_t)row * K + k0 + ccol * 8);
        }
    };

    issue(0); CP_COMMIT();
    if (NS > 1) { issue(1); CP_COMMIT(); }

    for (int s = 0; s < NS; s++) {
        if (s + 1 < NS) CP_WAIT1(); else CP_WAIT0();
        __syncthreads();
        if (s + 2 < NS) { issue(s + 2); CP_COMMIT(); }

        const int buf = s % NSTG;
        const uint32_t abase = sbase + buf * STG_HW * 2 + lmoff;
        const uint32_t bbase = abase + SA_STG * 2;

#pragma unroll
        for (int ks = 0; ks < 2; ks++) {
            uint32_t afr[4][4], bfr[NTL][2];
            const uint32_t koff = ks * 32;
#pragma unroll
            for (int mt = 0; mt < 4; mt++) {
                const uint32_t ad = abase + (wm + mt * 16) * 80 + koff;
                LDMX4(afr[mt][0], afr[mt][1], afr[mt][2], afr[mt][3], ad);
            }
#pragma unroll
            for (int np = 0; np < NTL / 2; np++) {
                const uint32_t bd = bbase + (wn + np * 16) * 80 + koff;
                LDMX4(bfr[2 * np][0], bfr[2 * np + 1][0],
                      bfr[2 * np][1], bfr[2 * np + 1][1], bd);
            }
#pragma unroll
            for (int mt = 0; mt < 4; mt++)
#pragma unroll
                for (int nt = 0; nt < NTL; nt++)
                    mma_f16_k16(acc[mt][nt], afr[mt], bfr[nt]);
        }
        __syncthreads();
    }

    const int g = lane >> 2, t = lane & 3;
    if (EPI == 1) {
        __half* C = (__half*)Cv;
#pragma unroll
        for (int mt = 0; mt < 4; mt++) {
            const int row0 = bm + wm + mt * 16 + g;
#pragma unroll
            for (int nt = 0; nt < NTL; nt++) {
                const int col = bn + wn + nt * 8 + 2 * t;
                const float2 e = *(const float2*)&E[col];
                *(__half2*)&C[(size_t)row0 * N + col] =
                    __floats2half2_rn(acc[mt][nt][0] + e.x, acc[mt][nt][1] + e.y);
                *(__half2*)&C[(size_t)(row0 + 8) * N + col] =
                    __floats2half2_rn(acc[mt][nt][2] + e.x, acc[mt][nt][3] + e.y);
            }
        }
    } else if (EPI == 2) {
        float* C = (float*)Cv;
#pragma unroll
        for (int mt = 0; mt < 4; mt++) {
            const int row0 = bm + wm + mt * 16 + g;
#pragma unroll
            for (int nt = 0; nt < NTL; nt++) {
                const int col = bn + wn + nt * 8 + 2 * t;
                const float2 e0 = *(const float2*)&E[(size_t)row0 * N + col];
                const float2 e1 = *(const float2*)&E[(size_t)(row0 + 8) * N + col];
                *(float2*)&C[(size_t)row0 * N + col] =
                    make_float2(acc[mt][nt][0] + e0.x, acc[mt][nt][1] + e0.y);
                *(float2*)&C[(size_t)(row0 + 8) * N + col] =
                    make_float2(acc[mt][nt][2] + e1.x, acc[mt][nt][3] + e1.y);
            }
        }
    } else {
        __half* C = (__half*)Cv;
#pragma unroll
        for (int mt = 0; mt < 4; mt++) {
            const int row0 = bm + wm + mt * 16 + g;
#pragma unroll
            for (int nt = 0; nt < NTL; nt += 2) {
                const int pcol = bn + wn + nt * 8;
                const int ocol = (pcol >> 4) * 8 + 2 * t;
                float v[4];
#pragma unroll
                for (int i = 0; i < 4; i++) {
                    const float gv = acc[mt][nt][i];
                    v[i] = gv / (1.f + __expf(-gv)) * acc[mt][nt + 1][i];
                }
                *(__half2*)&C[(size_t)row0 * IDIM + ocol] = __floats2half2_rn(v[0], v[1]);
                *(__half2*)&C[(size_t)(row0 + 8) * IDIM + ocol] = __floats2half2_rn(v[2], v[3]);
            }
        }
    }
}

// ===========================================================================
// RMSNorm: fp32 in, fp16 out
// ===========================================================================
__global__ __launch_bounds__(256) void rmsnorm_kernel(const float* __restrict__ x,
                                                      const float* __restrict__ w,
                                                      __half* __restrict__ out) {
    const size_t base = (size_t)blockIdx.x * HID;
    const float4* xr = (const float4*)(x + base);
    const float4* w4 = (const float4*)w;
    __half2* orow = (__half2*)(out + base);

    float4 v[4];
    float ss = 0.f;
#pragma unroll
    for (int it = 0; it < 4; it++) {
        v[it] = xr[threadIdx.x + 256 * it];
        ss += v[it].x * v[it].x + v[it].y * v[it].y + v[it].z * v[it].z + v[it].w * v[it].w;
    }
#pragma unroll
    for (int o = 16; o; o >>= 1) ss += __shfl_xor_sync(0xffffffffu, ss, o);

    __shared__ float warpsum[8];
    __shared__ float s_inv;
    const int lane = threadIdx.x & 31, wid = threadIdx.x >> 5;
    if (lane == 0) warpsum[wid] = ss;
    __syncthreads();
    if (threadIdx.x == 0) {
        float tsum = 0.f;
#pragma unroll
        for (int i = 0; i < 8; i++) tsum += warpsum[i];
        s_inv = rsqrtf(tsum * (1.0f / (float)HID) + 1e-6f);
    }
    __syncthreads();
    const float inv = s_inv;
#pragma unroll
    for (int it = 0; it < 4; it++) {
        const int idx = threadIdx.x + 256 * it;
        float4 wv = w4[idx];
        orow[idx * 2 + 0] = __floats2half2_rn(v[it].x * inv * wv.x, v[it].y * inv * wv.y);
        orow[idx * 2 + 1] = __floats2half2_rn(v[it].z * inv * wv.z, v[it].w * inv * wv.w);
    }
}

// ===========================================================================
// RoPE + split (fp16 in): q pre-scaled by log2e/sqrt(d), v transposed
// ===========================================================================
__global__ void rope_split_kernel(const __half* __restrict__ qkv,
                                  const int* __restrict__ positions,
                                  __half* __restrict__ q, __half* __restrict__ k,
                                  __half* __restrict__ vt) {
    const int row = blockIdx.x;
    const int h = blockIdx.y;
    const int d = threadIdx.x;   // 0..63
    const int b = row >> 10, s = row & (SEQ - 1);
    const float pos = (float)positions[s];
    const float freq = powf(10000.0f, -(float)d * (1.0f / 64.0f));
    float sn, cs;
    sincosf(pos * freq, &sn, &cs);
    const float scale = 0.08838834764831845f * LOG2E;

    const __half* base = qkv + (size_t)row * (3 * HID) + h * HDIM;
    const float q1 = __half2float(base[d]), q2 = __half2float(base[d + 64]);
    const float k1 = __half2float(base[HID + d]), k2 = __half2float(base[HID + d + 64]);

    const size_t hb = (size_t)(b * NHEAD + h);
    __half* qp = q + (hb * SEQ + s) * HDIM;
    __half* kp = k + (hb * SEQ + s) * HDIM;
    qp[d]      = __float2half_rn((q1 * cs - q2 * sn) * scale);
    qp[d + 64] = __float2half_rn((q2 * cs + q1 * sn) * scale);
    kp[d]      = __float2half_rn(k1 * cs - k2 * sn);
    kp[d + 64] = __float2half_rn(k2 * cs + k1 * sn);
    vt[(hb * HDIM + d) * SEQ + s]      = base[2 * HID + d];
    vt[(hb * HDIM + d + 64) * SEQ + s] = base[2 * HID + d + 64];
}

// ===========================================================================
// fp16 tensor-core flash attention (causal), log2-domain softmax.
// Heavy q-tiles scheduled first (qt reversed) to cut causal tail imbalance.
// ===========================================================================
#define QPW 68
#define VPW 36
#define AQ_OFF 0
#define AK_OFF (128 * 136)
#define AV_OFF (AK_OFF + 2 * 64 * 136)
#define ATTN_SMEM ((AV_OFF + 2 * 128 * 72) * 2)

__global__ __launch_bounds__(256, 1) void attn_mma_kernel(const __half* __restrict__ q,
                                                          const __half* __restrict__ k,
                                                          const __half* __restrict__ vt,
                                                          __half* __restrict__ attn) {
    extern __shared__ __half asm_[];
    const uint32_t sbase = smem_u32(asm_);
    const int tid = threadIdx.x;
    const int qt = gridDim.x - 1 - blockIdx.x;   // heavy tiles first
    const int h = blockIdx.y, b = blockIdx.z;
    const int w = tid >> 5, lane = tid & 31;
    const int g = lane >> 2, t = lane & 3;

    const size_t hb = (size_t)(b * NHEAD + h);
    const __half* qg = q + (hb * SEQ + qt * 128) * HDIM;
    const __half* kg = k + hb * SEQ * HDIM;
    const __half* vg = vt + hb * HDIM * SEQ;

    {
#pragma unroll
        for (int i = 0; i < 8; i++) {
            const int id = tid + i * 256;
            const int r = id >> 4, c = id & 15;
            cp16(sbase + AQ_OFF * 2 + r * 272 + c * 16, qg + (size_t)r * HDIM + c * 8);
        }
    }
    CP_COMMIT(); CP_WAIT0();
    __syncthreads();

    uint32_t afrQ[8][4];
    {
        const uint32_t* Qw = (const uint32_t*)(asm_ + AQ_OFF);
        const int r0 = 16 * w + g;
#pragma unroll
        for (int ks = 0; ks < 8; ks++) {
            afrQ[ks][0] = Qw[r0 * QPW + ks * 8 + t];
            afrQ[ks][1] = Qw[(r0 + 8) * QPW + ks * 8 + t];
            afrQ[ks][2] = Qw[r0 * QPW + ks * 8 + t + 4];
            afrQ[ks][3] = Qw[(r0 + 8) * QPW + ks * 8 + t + 4];
        }
    }
    __syncthreads();

    float O[16][4];
#pragma unroll
    for (int nt = 0; nt < 16; nt++)
#pragma unroll
        for (int i = 0; i < 4; i++) O[nt][i] = 0.f;
    float m0 = -1e30f, m1 = -1e30f, l0 = 0.f, l1 = 0.f;

    const int NT = 2 * qt + 2;

    auto issue = [&](int j) {
        const uint32_t kb = sbase + AK_OFF * 2 + (j & 1) * (64 * 136 * 2);
        const uint32_t vb = sbase + AV_OFF * 2 + (j & 1) * (128 * 72 * 2);
#pragma unroll
        for (int i = 0; i < 4; i++) {
            const int id = tid + i * 256;
            const int r = id >> 4, c = id & 15;
            cp16(kb + r * 272 + c * 16, kg + (size_t)(j * 64 + r) * HDIM + c * 8);
            const int d = id >> 3, c2 = id & 7;
            cp16(vb + d * 144 + c2 * 16, vg + (size_t)d * SEQ + j * 64 + c2 * 8);
        }
    };

    issue(0); CP_COMMIT();
    if (NT > 1) { issue(1); CP_COMMIT(); }

    const int rowg0 = qt * 128 + 16 * w + g;

    for (int j = 0; j < NT; j++) {
        if (j + 1 < NT) CP_WAIT1(); else CP_WAIT0();
        __syncthreads();

        const uint32_t* Kw = (const uint32_t*)(asm_ + AK_OFF + (j & 1) * 64 * 136);
        const uint32_t* Vw = (const uint32_t*)(asm_ + AV_OFF + (j & 1) * 128 * 72);

        float S[8][4];
#pragma unroll
        for (int nt = 0; nt < 8; nt++)
#pragma unroll
            for (int i = 0; i < 4; i++) S[nt][i] = 0.f;
#pragma unroll
        for (int ks = 0; ks < 8; ks++) {
            uint32_t bf[8][2];
#pragma unroll
            for (int nt = 0; nt < 8; nt++) {
                bf[nt][0] = Kw[(nt * 8 + g) * QPW + ks * 8 + t];
                bf[nt][1] = Kw[(nt * 8 + g) * QPW + ks * 8 + t + 4];
            }
#pragma unroll
            for (int nt = 0; nt < 8; nt++)
                mma_f16_k16(S[nt], afrQ[ks], bf[nt]);
        }

        if (j >= 2 * qt) {
#pragma unroll
            for (int nt = 0; nt < 8; nt++) {
                const int c0 = j * 64 + nt * 8 + 2 * t;
                if (c0 > rowg0)     S[nt][0] = -1e30f;
                if (c0 + 1 > rowg0) S[nt][1] = -1e30f;
                if (c0 > rowg0 + 8)     S[nt][2] = -1e30f;
                if (c0 + 1 > rowg0 + 8) S[nt][3] = -1e30f;
            }
        }

        float mx0 = -1e30f, mx1 = -1e30f;
#pragma unroll
        for (int nt = 0; nt < 8; nt++) {
            mx0 = fmaxf(mx0, fmaxf(S[nt][0], S[nt][1]));
            mx1 = fmaxf(mx1, fmaxf(S[nt][2], S[nt][3]));
        }
        mx0 = fmaxf(mx0, __shfl_xor_sync(0xffffffffu, mx0, 1));
        mx0 = fmaxf(mx0, __shfl_xor_sync(0xffffffffu, mx0, 2));
        mx1 = fmaxf(mx1, __shfl_xor_sync(0xffffffffu, mx1, 1));
        mx1 = fmaxf(mx1, __shfl_xor_sync(0xffffffffu, mx1, 2));
        const float mn0 = fmaxf(m0, mx0), mn1 = fmaxf(m1, mx1);
        const float cr0 = exp2f(m0 - mn0), cr1 = exp2f(m1 - mn1);

        uint32_t pf[4][4];
        float ps0 = 0.f, ps1 = 0.f;
#pragma unroll
        for (int nt = 0; nt < 8; nt++) {
            const uint32_t h01 = ex2h2(S[nt][0] - mn0, S[nt][1] - mn0);
            const uint32_t h23 = ex2h2(S[nt][2] - mn1, S[nt][3] - mn1);
            pf[nt >> 1][(nt & 1) ? 2 : 0] = h01;
            pf[nt >> 1][(nt & 1) ? 3 : 1] = h23;
            const float2 f01 = __half22float2(*(const __half2*)&h01);
            const float2 f23 = __half22float2(*(const __half2*)&h23);
            ps0 += f01.x + f01.y;
            ps1 += f23.x + f23.y;
        }
        ps0 += __shfl_xor_sync(0xffffffffu, ps0, 1);
        ps0 += __shfl_xor_sync(0xffffffffu, ps0, 2);
        ps1 += __shfl_xor_sync(0xffffffffu, ps1, 1);
        ps1 += __shfl_xor_sync(0xffffffffu, ps1, 2);
        l0 = l0 * cr0 + ps0;
        l1 = l1 * cr1 + ps1;
        m0 = mn0; m1 = mn1;
#pragma unroll
        for (int nt = 0; nt < 16; nt++) {
            O[nt][0] *= cr0; O[nt][1] *= cr0;
            O[nt][2] *= cr1; O[nt][3] *= cr1;
        }

#pragma unroll
        for (int kk = 0; kk < 4; kk++) {
#pragma unroll
            for (int nt = 0; nt < 16; nt++) {
                uint32_t bv[2];
                bv[0] = Vw[(nt * 8 + g) * VPW + kk * 8 + t];
                bv[1] = Vw[(nt * 8 + g) * VPW + kk * 8 + t + 4];
                mma_f16_k16(O[nt], pf[kk], bv);
            }
        }

        __syncthreads();
        if (j + 2 < NT) { issue(j + 2); CP_COMMIT(); }
    }

    const float inv0 = 1.0f / l0, inv1 = 1.0f / l1;
    __half* orow0 = attn + ((size_t)(b * SEQ + qt * 128 + 16 * w + g)) * HID + h * HDIM;
    __half* orow1 = orow0 + 8 * HID;
#pragma unroll
    for (int nt = 0; nt < 16; nt++) {
        const int c = nt * 8 + 2 * t;
        *(__half2*)&orow0[c] = __floats2half2_rn(O[nt][0] * inv0, O[nt][1] * inv0);
        *(__half2*)&orow1[c] = __floats2half2_rn(O[nt][2] * inv1, O[nt][3] * inv1);
    }
}

// ===========================================================================
// Launch
// ===========================================================================
extern "C" void kernel_launch(void* const* d_in, const int* in_sizes, int n_in,
                              void* d_out, int out_size) {
    const int*   positions = (const int*)  d_in[0];
    const float* hidden    = (const float*)d_in[1];
    const float* ln1       = (const float*)d_in[2];
    const float* ln2       = (const float*)d_in[3];
    const float* w_qkv     = (const float*)d_in[4];
    const float* b_qkv     = (const float*)d_in[5];
    const float* w_o       = (const float*)d_in[6];
    const float* w_gu      = (const float*)d_in[7];
    const float* w_down    = (const float*)d_in[8];
    float* out = (float*)d_out;

    void* p;
    cudaGetSymbolAddress(&p, g_x);    __half* x    = (__half*)p;
    cudaGetSymbolAddress(&p, g_qkv);  __half* qkv  = (__half*)p;
    cudaGetSymbolAddress(&p, g_q);    __half* qh   = (__half*)p;
    cudaGetSymbolAddress(&p, g_k);    __half* kh   = (__half*)p;
    cudaGetSymbolAddress(&p, g_vt);   __half* vth  = (__half*)p;
    cudaGetSymbolAddress(&p, g_attn); __half* attn = (__half*)p;
    cudaGetSymbolAddress(&p, g_x2);   float*  x2   = (float*)p;
    cudaGetSymbolAddress(&p, g_mlp);  __half* mlp  = (__half*)p;
    cudaGetSymbolAddress(&p, g_wT);   __half* wT   = (__half*)p;
    __half* qkvT = wT + WT_QKV;
    __half* oT   = wT + WT_O;
    __half* guT  = wT + WT_GU;
    __half* dnT  = wT + WT_DN;

    cudaFuncSetAttribute(attn_mma_kernel, cudaFuncAttributeMaxDynamicSharedMemorySize, ATTN_SMEM);
    cudaFuncSetAttribute((const void*)mma_gemm_kernel<1, 8>,
                         cudaFuncAttributeMaxDynamicSharedMemorySize, GEMM_SMEM_N8);
    cudaFuncSetAttribute((const void*)mma_gemm_kernel<3, 8>,
                         cudaFuncAttributeMaxDynamicSharedMemorySize, GEMM_SMEM_N8);
    cudaFuncSetAttribute((const void*)mma_gemm_kernel<2, 4>,
                         cudaFuncAttributeMaxDynamicSharedMemorySize, GEMM_SMEM_N4);

    // ---- fork: weight transposes on s1 ----
    cudaEventRecord(g_ar.evRoot, 0);
    cudaStreamWaitEvent(g_ar.s1, g_ar.evRoot, 0);
    transpose_h_kernel<0><<<dim3((3 * HID) / 32, HID / 32), 256, 0, g_ar.s1>>>(
        w_qkv, qkvT, HID, 3 * HID);
    cudaEventRecord(g_ar.evQ, g_ar.s1);
    transpose_h_kernel<0><<<dim3(HID / 32, HID / 32), 256, 0, g_ar.s1>>>(w_o, oT, HID, HID);
    transpose_h_kernel<1><<<dim3((2 * IDIM) / 32, HID / 32), 256, 0, g_ar.s1>>>(
        w_gu, guT, HID, 2 * IDIM);
    transpose_h_kernel<0><<<dim3(HID / 32, IDIM / 32), 256, 0, g_ar.s1>>>(w_down, dnT, IDIM, HID);
    cudaEventRecord(g_ar.evW, g_ar.s1);

    // ---- main chain on stream 0 ----
    rmsnorm_kernel<<<MROWS, 256>>>(hidden, ln1, x);
    cudaStreamWaitEvent(0, g_ar.evQ, 0);
    // qkv = x @ w_qkv + b_qkv
    if (g_tc.ok)
        tc_gemm_launch(x, qkvT, b_qkv, qkv, MROWS, 3 * HID, HID, 1);
    else
        mma_gemm_kernel<1, 8><<<dim3((3 * HID) / 256, MROWS / GBM), 256, GEMM_SMEM_N8>>>(
            x, qkvT, b_qkv, qkv, MROWS, 3 * HID, HID);
    rope_split_kernel<<<dim3(MROWS, NHEAD), 64>>>(qkv, positions, qh, kh, vth);
    attn_mma_kernel<<<dim3(SEQ / 128, NHEAD, BZ), 256, ATTN_SMEM>>>(qh, kh, vth, attn);
    cudaStreamWaitEvent(0, g_ar.evW, 0);
    // x2 = hidden + attn @ w_o
    if (g_tc.ok)
        tc_gemm_launch(attn, oT, hidden, x2, MROWS, HID, HID, 2);
    else
        mma_gemm_kernel<2, 4><<<dim3(HID / 128, MROWS / GBM), 256, GEMM_SMEM_N4>>>(
            attn, oT, hidden, x2, MROWS, HID, HID);
    rmsnorm_kernel<<<MROWS, 256>>>(x2, ln2, x);
    // mlp = silu(gate)*up fused
    if (g_tc.ok)
        tc_gemm_launch(x, guT, nullptr, mlp, MROWS, 2 * IDIM, HID, 3);
    else
        mma_gemm_kernel<3, 8><<<dim3((2 * IDIM) / 256, MROWS / GBM), 256, GEMM_SMEM_N8>>>(
            x, guT, nullptr, mlp, MROWS, 2 * IDIM, HID);
    // out = x2 + mlp @ w_down
    if (g_tc.ok)
        tc_gemm_launch(mlp, dnT, x2, out, MROWS, HID, IDIM, 2);
    else
        mma_gemm_kernel<2, 4><<<dim3(HID / 128, MROWS / GBM), 256, GEMM_SMEM_N4>>>(
            mlp, dnT, x2, out, MROWS, HID, IDIM);
}

// round 17
// speedup vs baseline: 1.3056x; 1.0574x over previous
#include <cuda_runtime.h>
#include <cuda_fp16.h>
#include <cstdint>
#include <cstdlib>
#include <cstring>
#include <math.h>
#include <dlfcn.h>

// Problem constants
#define BZ    2
#define SEQ   1024
#define HID   4096
#define NHEAD 32
#define HDIM  128
#define IDIM  11008
#define MROWS 2048            // B*S
#define LOG2E 1.4426950408889634f

// ===========================================================================
// Scratch (static device memory — no allocation anywhere in kernel_launch)
// ===========================================================================
__device__ __align__(16) __half g_x   [(size_t)MROWS * HID];
__device__ __align__(16) __half g_qkv [(size_t)MROWS * 3 * HID];
__device__ __align__(16) __half g_q   [(size_t)MROWS * HID];      // [b][h][s][d]
__device__ __align__(16) __half g_k   [(size_t)MROWS * HID];      // [b][h][s][d]
__device__ __align__(16) __half g_vt  [(size_t)MROWS * HID];      // [b][h][d][s]
__device__ __align__(16) __half g_attn[(size_t)MROWS * HID];      // [b][s][h][d]
__device__ __align__(16) float  g_x2  [(size_t)MROWS * HID];
__device__ __align__(16) __half g_mlp [(size_t)MROWS * IDIM];
#define WT_QKV 0
#define WT_O   ((size_t)3 * HID * HID)
#define WT_GU  (WT_O + (size_t)HID * HID)
#define WT_DN  (WT_GU + (size_t)HID * 2 * IDIM)
#define WT_TOT (WT_DN + (size_t)HID * IDIM)
__device__ __align__(16) __half g_wT[WT_TOT];

// ===========================================================================
// NVRTC-JIT tcgen05 GEMM (sm_103a), cta_group::2, 3-stage pipeline
// (round-16 proven configuration, frozen).
// ===========================================================================
static const char* TC_SRC = R"XX(
typedef unsigned int u32;
typedef unsigned long long u64;
typedef unsigned short u16;

__device__ __forceinline__ float uf(u32 u) {
    float f; asm("mov.b32 %0, %1;" : "=f"(f) : "r"(u)); return f;
}

extern "C" __global__ void __launch_bounds__(256) tc_gemm(
    const u16* __restrict__ A, const u16* __restrict__ BT,
    const float* __restrict__ E, void* Cv, int M, int N, int K, int EPI)
{
    extern __shared__ unsigned char smem[];
    u32 smb;
    asm("{ .reg .u64 t; cvta.to.shared.u64 t, %1; cvt.u32.u64 %0, t; }" : "=r"(smb) : "l"(smem));
    const int tid = threadIdx.x;
    const int bm = blockIdx.x * 128;
    const int bn = blockIdx.y * 256;
    const int NS = K >> 6;
    u32 rank;
    asm("mov.u32 %0, %%cluster_ctarank;" : "=r"(rank));

    const u32 TMP = smb;
    const u32 FULLB = smb + 8;
    const u32 DONEB = smb + 32;
    const u32 DATA0 = smb + 1024;

    if (tid < 32) {
        asm volatile("tcgen05.alloc.cta_group::2.sync.aligned.shared::cta.b32 [%0], %1;"
                     :: "r"(TMP), "r"(256) : "memory");
        asm volatile("tcgen05.relinquish_alloc_permit.cta_group::2.sync.aligned;");
    }
    if (tid == 0) {
        #pragma unroll
        for (int s = 0; s < 3; s++) {
            asm volatile("mbarrier.init.shared.b64 [%0], 2;" :: "r"(FULLB + 8 * s) : "memory");
            asm volatile("mbarrier.init.shared.b64 [%0], 1;" :: "r"(DONEB + 8 * s) : "memory");
        }
    }
    __syncthreads();
    asm volatile("barrier.cluster.arrive.aligned;" ::: "memory");
    asm volatile("barrier.cluster.wait.aligned;" ::: "memory");

    u32 tmem;
    asm volatile("ld.shared.b32 %0, [%1];" : "=r"(tmem) : "r"(TMP));

    const u16* Ap = A + (u64)bm * K;
    const u16* Bp = BT + (u64)(bn + rank * 128) * K;

    u32 el = 0;
    if (tid < 32)
        asm volatile("{\n .reg .pred p;\n elect.sync _|p, 0xFFFFFFFF;\n selp.b32 %0, 1, 0, p;\n}"
                     : "=r"(el));

    #define ISSUE(s) do {                                                        \
        const int k0_ = (s) << 6;                                                \
        const u32 as_ = DATA0 + (u32)((s) % 3) * 32768u;                         \
        const u32 bs_ = as_ + 16384u;                                            \
        for (int j = 0; j < 4; j++) {                                            \
            int c = tid + j * 256;                                               \
            int row = c >> 3, col = c & 7;                                       \
            u32 off = (u32)(row * 128 + col * 16); off ^= (off >> 3) & 0x70;     \
            asm volatile("cp.async.cg.shared.global [%0], [%1], 16;"             \
                         :: "r"(as_ + off), "l"(Ap + (u64)row * K + k0_ + col * 8)); \
        }                                                                        \
        for (int j = 0; j < 4; j++) {                                            \
            int c = tid + j * 256;                                               \
            int row = c >> 3, col = c & 7;                                       \
            u32 off = (u32)(row * 128 + col * 16); off ^= (off >> 3) & 0x70;     \
            asm volatile("cp.async.cg.shared.global [%0], [%1], 16;"             \
                         :: "r"(bs_ + off), "l"(Bp + (u64)row * K + k0_ + col * 8)); \
        }                                                                        \
        asm volatile("cp.async.commit_group;" ::: "memory");                     \
    } while (0)

    #define MWAIT(addr, ph) do {                                                 \
        u32 done_;                                                               \
        asm volatile("{\n .reg .pred p;\n"                                       \
            " mbarrier.try_wait.parity.acquire.cta.shared::cta.b64 p, [%1], %2;\n" \
            " selp.b32 %0, 1, 0, p;\n}" : "=r"(done_) : "r"(addr), "r"((u32)(ph)) : "memory"); \
        while (!done_) {                                                         \
            asm volatile("{\n .reg .pred p;\n"                                   \
                " mbarrier.try_wait.parity.acquire.cta.shared::cta.b64 p, [%1], %2;\n" \
                " selp.b32 %0, 1, 0, p;\n}" : "=r"(done_) : "r"(addr), "r"((u32)(ph)) : "memory"); \
        }                                                                        \
    } while (0)

    ISSUE(0);
    if (NS > 1) ISSUE(1);

    int fp[3] = {0, 0, 0};
    int dp[3] = {0, 0, 0};
    const u16 msk = 3;

    for (int i = 0; i < NS; i++) {
        if (i + 1 < NS)
            asm volatile("cp.async.wait_group 1;" ::: "memory");
        else
            asm volatile("cp.async.wait_group 0;" ::: "memory");
        __syncthreads();
        asm volatile("fence.proxy.async.shared::cta;" ::: "memory");
        const int buf = i % 3;
        const u32 FULL = FULLB + 8 * buf;
        const u32 DONE = DONEB + 8 * buf;
        if (tid == 0) {
            asm volatile("{\n .reg .b32 ra;\n"
                " mapa.shared::cluster.u32 ra, %0, 0;\n"
                " mbarrier.arrive.shared::cluster.b64 _, [ra];\n}"
                :: "r"(FULL) : "memory");
        }
        if (rank == 0 && el) {
            MWAIT(FULL, fp[buf]);
            const u64 DB = (2ULL << 61) | (1ULL << 46) | (64ULL << 32) | (1ULL << 16);
            const u32 as_ = DATA0 + (u32)buf * 32768u;
            u64 ad = DB | (u64)((as_ >> 4) & 0x3FFF);
            u64 bd = DB | (u64)(((as_ + 16384u) >> 4) & 0x3FFF);
            #pragma unroll
            for (int k = 0; k < 4; k++) {
                u32 en = (i > 0 || k > 0) ? 1u : 0u;
                asm volatile("{\n .reg .pred p;\n setp.ne.u32 p, %5, 0;\n"
                    " tcgen05.mma.cta_group::2.kind::f16 [%0], %1, %2, %3, "
                    "{%4, %4, %4, %4, %4, %4, %4, %4}, p;\n}"
                    :: "r"(tmem), "l"(ad + 2 * k), "l"(bd + 2 * k),
                       "r"(0x10400010u), "r"(0u), "r"(en) : "memory");
            }
            asm volatile("tcgen05.commit.cta_group::2.mbarrier::arrive::one"
                ".shared::cluster.multicast::cluster.b64 [%0], %1;"
                :: "r"(DONE), "h"(msk) : "memory");
        }
        fp[buf] ^= 1;
        if (i + 2 < NS) {
            if (i >= 1) {
                const int wb = (i - 1) % 3;
                MWAIT(DONEB + 8 * wb, dp[wb]);
                dp[wb] ^= 1;
            }
            ISSUE(i + 2);
        }
    }
    {
        const int lb = (NS - 1) % 3;
        MWAIT(DONEB + 8 * lb, dp[lb]);
    }
    asm volatile("tcgen05.fence::after_thread_sync;" ::: "memory");

    const int w = tid >> 5, lane = tid & 31;
    const int grow = bm + (w & 3) * 32 + lane;
    const int cbase = (w >> 2) * 128;
    for (int ch = 0; ch < 4; ch++) {
        u32 r[32];
        asm volatile("tcgen05.ld.sync.aligned.32x32b.x32.b32 "
            "{%0,%1,%2,%3,%4,%5,%6,%7,%8,%9,%10,%11,%12,%13,%14,%15,"
            "%16,%17,%18,%19,%20,%21,%22,%23,%24,%25,%26,%27,%28,%29,%30,%31}, [%32];"
            : "=r"(r[0]),  "=r"(r[1]),  "=r"(r[2]),  "=r"(r[3]),
              "=r"(r[4]),  "=r"(r[5]),  "=r"(r[6]),  "=r"(r[7]),
              "=r"(r[8]),  "=r"(r[9]),  "=r"(r[10]), "=r"(r[11]),
              "=r"(r[12]), "=r"(r[13]), "=r"(r[14]), "=r"(r[15]),
              "=r"(r[16]), "=r"(r[17]), "=r"(r[18]), "=r"(r[19]),
              "=r"(r[20]), "=r"(r[21]), "=r"(r[22]), "=r"(r[23]),
              "=r"(r[24]), "=r"(r[25]), "=r"(r[26]), "=r"(r[27]),
              "=r"(r[28]), "=r"(r[29]), "=r"(r[30]), "=r"(r[31])
            : "r"(tmem + (u32)(cbase + ch * 32)));
        asm volatile("tcgen05.wait::ld.sync.aligned;" ::: "memory");
        const int gcol = bn + cbase + ch * 32;
        if (EPI == 1) {
            u16* C = (u16*)Cv;
            const u64 ob = (u64)grow * (u64)N + (u64)gcol;
            #pragma unroll
            for (int q = 0; q < 4; q++) {
                u32 pk[4];
                #pragma unroll
                for (int d = 0; d < 4; d++) {
                    const int j = q * 8 + d * 2;
                    float v0 = uf(r[j]) + E[gcol + j];
                    float v1 = uf(r[j + 1]) + E[gcol + j + 1];
                    u16 h0, h1;
                    asm("cvt.rn.f16.f32 %0, %1;" : "=h"(h0) : "f"(v0));
                    asm("cvt.rn.f16.f32 %0, %1;" : "=h"(h1) : "f"(v1));
                    pk[d] = (u32)h0 | ((u32)h1 << 16);
                }
                asm volatile("st.global.v4.b32 [%0], {%1,%2,%3,%4};"
                             :: "l"(C + ob + q * 8), "r"(pk[0]), "r"(pk[1]), "r"(pk[2]), "r"(pk[3]));
            }
        } else if (EPI == 2) {
            float* C = (float*)Cv;
            const u64 ob = (u64)grow * (u64)N + (u64)gcol;
            #pragma unroll
            for (int q = 0; q < 8; q++) {
                float e0, e1, e2, e3;
                asm("ld.global.v4.f32 {%0,%1,%2,%3}, [%4];"
                    : "=f"(e0), "=f"(e1), "=f"(e2), "=f"(e3) : "l"(E + ob + q * 4));
                float v0 = uf(r[q * 4 + 0]) + e0;
                float v1 = uf(r[q * 4 + 1]) + e1;
                float v2 = uf(r[q * 4 + 2]) + e2;
                float v3 = uf(r[q * 4 + 3]) + e3;
                asm volatile("st.global.v4.f32 [%0], {%1,%2,%3,%4};"
                             :: "l"(C + ob + q * 4), "f"(v0), "f"(v1), "f"(v2), "f"(v3));
            }
        } else {
            u16* C = (u16*)Cv;
            const int l0 = (gcol >> 4) * 8;
            const u64 ob = (u64)grow * 11008ULL + (u64)l0;
            u32 pk[8];
            #pragma unroll
            for (int gi = 0; gi < 16; gi++) {
                const int j = (gi < 8) ? gi : (gi + 8);
                float gv = uf(r[j]);
                float up = uf(r[j + 8]);
                float t;
                asm("ex2.approx.f32 %0, %1;" : "=f"(t) : "f"(-1.4426950408889634f * gv));
                float v = gv / (1.0f + t) * up;
                u16 h;
                asm("cvt.rn.f16.f32 %0, %1;" : "=h"(h) : "f"(v));
                if (gi & 1) pk[gi >> 1] |= ((u32)h << 16);
                else        pk[gi >> 1] = (u32)h;
            }
            asm volatile("st.global.v4.b32 [%0], {%1,%2,%3,%4};"
                         :: "l"(C + ob), "r"(pk[0]), "r"(pk[1]), "r"(pk[2]), "r"(pk[3]));
            asm volatile("st.global.v4.b32 [%0], {%1,%2,%3,%4};"
                         :: "l"(C + ob + 8), "r"(pk[4]), "r"(pk[5]), "r"(pk[6]), "r"(pk[7]));
        }
    }
    asm volatile("tcgen05.fence::before_thread_sync;" ::: "memory");
    __syncthreads();
    if (tid < 32)
        asm volatile("tcgen05.dealloc.cta_group::2.sync.aligned.b32 %0, %1;"
                     :: "r"(tmem), "r"(256));
    asm volatile("barrier.cluster.arrive.aligned;" ::: "memory");
    asm volatile("barrier.cluster.wait.aligned;" ::: "memory");
}
)XX";

typedef int nvrtcResult_;
typedef void* nvrtcProg_;
typedef nvrtcResult_ (*PFN_nvrtcCreateProgram)(nvrtcProg_*, const char*, const char*,
    int, const char* const*, const char* const*);
typedef nvrtcResult_ (*PFN_nvrtcCompileProgram)(nvrtcProg_, int, const char* const*);
typedef nvrtcResult_ (*PFN_nvrtcGetCUBINSize)(nvrtcProg_, size_t*);
typedef nvrtcResult_ (*PFN_nvrtcGetCUBIN)(nvrtcProg_, char*);

#define TC_SMEM 99328

struct TcJit {
    bool ok = false;
    cudaKernel_t kern = nullptr;

    static void launch_raw(cudaKernel_t k, const void* A, const void* BT, const void* E,
                           void* C, int M, int N, int K, int EPI, cudaStream_t s) {
        cudaLaunchConfig_t cfg = {};
        cfg.gridDim = dim3((unsigned)(M / 128), (unsigned)(N / 256), 1);
        cfg.blockDim = dim3(256, 1, 1);
        cfg.dynamicSmemBytes = TC_SMEM;
        cfg.stream = s;
        cudaLaunchAttribute attrs[1];
        attrs[0].id = cudaLaunchAttributeClusterDimension;
        attrs[0].val.clusterDim.x = 2;
        attrs[0].val.clusterDim.y = 1;
        attrs[0].val.clusterDim.z = 1;
        cfg.attrs = attrs;
        cfg.numAttrs = 1;
        void* a = (void*)A; void* b = (void*)BT; void* e = (void*)E; void* c = C;
        void* params[8] = {&a, &b, &e, &c, &M, &N, &K, &EPI};
        cudaLaunchKernelExC(&cfg, (const void*)k, params);
    }

    TcJit() {
        void* hn = dlopen("libnvrtc.so.13", RTLD_NOW | RTLD_GLOBAL);
        if (!hn) hn = dlopen("libnvrtc.so", RTLD_NOW | RTLD_GLOBAL);
        if (!hn) hn = dlopen("libnvrtc.so.12", RTLD_NOW | RTLD_GLOBAL);
        if (!hn) return;
        auto pCreate  = (PFN_nvrtcCreateProgram)dlsym(hn, "nvrtcCreateProgram");
        auto pCompile = (PFN_nvrtcCompileProgram)dlsym(hn, "nvrtcCompileProgram");
        auto pSize    = (PFN_nvrtcGetCUBINSize)dlsym(hn, "nvrtcGetCUBINSize");
        auto pGet     = (PFN_nvrtcGetCUBIN)dlsym(hn, "nvrtcGetCUBIN");
        if (!pCreate || !pCompile || !pSize || !pGet) return;
        nvrtcProg_ prog = nullptr;
        if (pCreate(&prog, TC_SRC, "tc.cu", 0, nullptr, nullptr) != 0) return;
        const char* opts[] = {"--gpu-architecture=sm_103a", "--std=c++17"};
        if (pCompile(prog, 2, opts) != 0) return;
        size_t sz = 0;
        if (pSize(prog, &sz) != 0 || sz == 0) return;
        char* cubin = (char*)malloc(sz);
        if (!cubin || pGet(prog, cubin) != 0) return;

        cudaLibrary_t lib = nullptr;
        if (cudaLibraryLoadData(&lib, cubin, nullptr, nullptr, 0, nullptr, nullptr, 0)
            != cudaSuccess) return;
        if (cudaLibraryGetKernel(&kern, lib, "tc_gemm") != cudaSuccess || !kern) return;
        if (cudaFuncSetAttribute((const void*)kern,
                                 cudaFuncAttributeMaxDynamicSharedMemorySize,
                                 TC_SMEM) != cudaSuccess) return;

        // ---- numeric self-test: M=256 cluster pair, N=256, K=256 (NS=4) ----
        const int M = 256, N = 256, K = 256;
        __half *dA = nullptr, *dBT = nullptr, *dC = nullptr;
        float* dE = nullptr;
        if (cudaMalloc(&dA, (size_t)M * K * 2)) return;
        if (cudaMalloc(&dBT, (size_t)N * K * 2)) return;
        if (cudaMalloc(&dC, (size_t)M * N * 2)) return;
        if (cudaMalloc(&dE, (size_t)N * 4)) return;
        __half* hA = (__half*)malloc((size_t)M * K * 2);
        __half* hB = (__half*)malloc((size_t)N * K * 2);
        float*  hE = (float*)malloc((size_t)N * 4);
        __half* hC = (__half*)malloc((size_t)M * N * 2);
        for (int i = 0; i < M * K; i++)
            hA[i] = __float2half_rn(0.1f * (float)((i * 7 + 3) % 13 - 6));
        for (int i = 0; i < N * K; i++)
            hB[i] = __float2half_rn(0.05f * (float)((i * 5 + 11) % 17 - 8));
        for (int i = 0; i < N; i++) hE[i] = 0.01f * (float)i;
        cudaMemcpy(dA, hA, (size_t)M * K * 2, cudaMemcpyHostToDevice);
        cudaMemcpy(dBT, hB, (size_t)N * K * 2, cudaMemcpyHostToDevice);
        cudaMemcpy(dE, hE, (size_t)N * 4, cudaMemcpyHostToDevice);
        cudaMemset(dC, 0, (size_t)M * N * 2);
        launch_raw(kern, dA, dBT, dE, dC, M, N, K, 1, 0);
        if (cudaDeviceSynchronize() != cudaSuccess) { cudaGetLastError(); goto cleanup; }
        if (cudaGetLastError() != cudaSuccess) goto cleanup;
        cudaMemcpy(hC, dC, (size_t)M * N * 2, cudaMemcpyDeviceToHost);
        {
            bool good = true;
            for (int r = 0; r < M && good; r += 7) {
                for (int n = 0; n < N && good; n += 11) {
                    float ref = hE[n];
                    for (int k = 0; k < K; k++)
                        ref += __half2float(hA[r * K + k]) * __half2float(hB[n * K + k]);
                    float got = __half2float(hC[r * N + n]);
                    if (fabsf(got - ref) > 0.08f + 0.02f * fabsf(ref)) good = false;
                }
            }
            if (good) ok = true;
        }
    cleanup:
        cudaFree(dA); cudaFree(dBT); cudaFree(dC); cudaFree(dE);
        free(hA); free(hB); free(hE); free(hC);
    }
};
static TcJit g_tc;

static inline void tc_gemm_launch(const __half* A, const __half* BT, const float* E,
                                  void* C, int M, int N, int K, int EPI) {
    TcJit::launch_raw(g_tc.kern, A, BT, E, C, M, N, K, EPI, 0);
}

// Host-side stream/event resources (created before harness mem baseline).
struct AsyncRes {
    cudaStream_t s1;
    cudaEvent_t evRoot, evQ, evW;
    AsyncRes() {
        cudaStreamCreateWithFlags(&s1, cudaStreamNonBlocking);
        cudaEventCreateWithFlags(&evRoot, cudaEventDisableTiming);
        cudaEventCreateWithFlags(&evQ, cudaEventDisableTiming);
        cudaEventCreateWithFlags(&evW, cudaEventDisableTiming);
    }
};
static AsyncRes g_ar;

__device__ __forceinline__ uint32_t smem_u32(const void* p) {
    uint32_t a;
    asm("{ .reg .u64 t; cvta.to.shared.u64 t, %1; cvt.u32.u64 %0, t; }" : "=r"(a) : "l"(p));
    return a;
}
__device__ __forceinline__ void cp16(uint32_t dst, const void* src) {
    asm volatile("cp.async.cg.shared.global [%0], [%1], 16;" :: "r"(dst), "l"(src));
}
#define CP_COMMIT() asm volatile("cp.async.commit_group;" ::: "memory")
#define CP_WAIT1()  asm volatile("cp.async.wait_group 1;" ::: "memory")
#define CP_WAIT0()  asm volatile("cp.async.wait_group 0;" ::: "memory")

__device__ __forceinline__ void mma_f16_k16(float* c, const uint32_t* a, const uint32_t* b) {
    asm volatile("mma.sync.aligned.m16n8k16.row.col.f32.f16.f16.f32 "
                 "{%0,%1,%2,%3}, {%4,%5,%6,%7}, {%8,%9}, {%0,%1,%2,%3};"
                 : "+f"(c[0]), "+f"(c[1]), "+f"(c[2]), "+f"(c[3])
                 : "r"(a[0]), "r"(a[1]), "r"(a[2]), "r"(a[3]), "r"(b[0]), "r"(b[1]));
}
#define LDMX4(r0, r1, r2, r3, addr) \
    asm volatile("ldmatrix.sync.aligned.m8n8.x4.shared.b16 {%0,%1,%2,%3}, [%4];" \
                 : "=r"(r0), "=r"(r1), "=r"(r2), "=r"(r3) : "r"(addr))

__device__ __forceinline__ uint32_t ex2h2(float a, float b) {
    __half2 h = __floats2half2_rn(a, b);
    uint32_t u = *(uint32_t*)&h, r;
    asm("ex2.approx.f16x2 %0, %1;" : "=r"(r) : "r"(u));
    return r;
}

// ===========================================================================
// Weight transpose + fp16: src fp32 [K][N] -> dst fp16 [N][K]
// MODE 0: direct; MODE 1: gate/up interleave
// ===========================================================================
template <int MODE>
__global__ __launch_bounds__(256) void transpose_h_kernel(const float* __restrict__ src,
                                                          __half* __restrict__ dst,
                                                          int K, int N) {
    __shared__ float tile[32][33];
    const int bx = blockIdx.x * 32;
    const int by = blockIdx.y * 32;
    const int tx = threadIdx.x & 31, ty = threadIdx.x >> 5;
#pragma unroll
    for (int j = 0; j < 32; j += 8)
        tile[ty + j][tx] = src[(size_t)(by + ty + j) * N + bx + tx];
    __syncthreads();
#pragma unroll
    for (int j = 0; j < 32; j += 8) {
        int n = bx + ty + j;
        int m;
        if (MODE == 1)
            m = (n < IDIM) ? ((n >> 3) * 16 + (n & 7))
                           : (((n - IDIM) >> 3) * 16 + 8 + (n & 7));
        else
            m = n;
        dst[(size_t)m * K + by + tx] = __float2half_rn(tile[tx][ty + j]);
    }
}

// ===========================================================================
// V transpose: qkv V slice [b][s][h][d] (fp16) -> vt [b][h][d][s] (fp16)
// smem-tiled 32x32: both global accesses coalesced. Replaces the 2-byte
// scattered writes previously done in rope_split.
// ===========================================================================
__global__ __launch_bounds__(256) void v_transpose_kernel(const __half* __restrict__ qkv,
                                                          __half* __restrict__ vt) {
    __shared__ __half tile[32][33];
    const int s0 = blockIdx.x * 32;
    const int d0 = blockIdx.y * 32;
    const int bh = blockIdx.z;              // b*NHEAD + h
    const int b = bh >> 5, h = bh & 31;
    const int tx = threadIdx.x & 31, ty = threadIdx.x >> 5;

    // read: rows s, cols d (d contiguous)
#pragma unroll
    for (int j = 0; j < 32; j += 8) {
        const size_t row = (size_t)(b * SEQ + s0 + ty + j);
        tile[ty + j][tx] = qkv[row * (3 * HID) + 2 * HID + h * HDIM + d0 + tx];
    }
    __syncthreads();
    // write: rows d, cols s (s contiguous)
    __half* dst = vt + ((size_t)bh * HDIM) * SEQ;
#pragma unroll
    for (int j = 0; j < 32; j += 8)
        dst[(size_t)(d0 + ty + j) * SEQ + s0 + tx] = tile[tx][ty + j];
}

// ===========================================================================
// FALLBACK fp16 mma.sync GEMM
// ===========================================================================
#define GBM 128
#define GBK 32
#define HPITCH 40
#define SA_STG (GBM * HPITCH)
#define NSTG 3
#define GEMM_SMEM_N8 (NSTG * (SA_STG + 256 * HPITCH) * 2)
#define GEMM_SMEM_N4 (NSTG * (SA_STG + 128 * HPITCH) * 2)

template <int EPI, int NTL>
__global__ __launch_bounds__(256, (NTL == 4) ? 2 : 1)
void mma_gemm_kernel(const __half* __restrict__ A,
                     const __half* __restrict__ BT,
                     const float* __restrict__ E,
                     void* __restrict__ Cv,
                     int M, int N, int K) {
    constexpr int BN = NTL * 32;
    constexpr int SB_STG = BN * HPITCH;
    constexpr int STG_HW = SA_STG + SB_STG;
    extern __shared__ __half smem[];

    const int tid = threadIdx.x;
    const int bm = blockIdx.y * GBM;
    const int bn = blockIdx.x * BN;
    const int w = tid >> 5, lane = tid & 31;
    const int wm = (w & 1) * 64;
    const int wn = (w >> 1) * (NTL * 8);

    const int quad = lane >> 3;
    const int qr = (quad & 1) * 8 + (lane & 7);
    const int qk = (quad >> 1) * 8;
    const uint32_t lmoff = (uint32_t)(qr * HPITCH + qk) * 2;

    const __half* Ap = A + (size_t)bm * K;
    const __half* Bp = BT + (size_t)bn * K;
    const int NS = K / GBK;

    const int crow = tid >> 2;
    const int ccol = tid & 3;
    const uint32_t sbase = smem_u32(smem);

    float acc[4][NTL][4];
#pragma unroll
    for (int mt = 0; mt < 4; mt++)
#pragma unroll
        for (int nt = 0; nt < NTL; nt++)
#pragma unroll
            for (int i = 0; i < 4; i++) acc[mt][nt][i] = 0.f;

    auto issue = [&](int s) {
        const int buf = s % NSTG;
        const int k0 = s * GBK;
        const uint32_t sa = sbase + buf * STG_HW * 2;
        const uint32_t sb = sa + SA_STG * 2;
#pragma unroll
        for (int j = 0; j < 2; j++) {
            const int row = crow + j * 64;
            cp16(sa + row * 80 + ccol * 16, Ap + (size_t)row * K + k0 + ccol * 8);
        }
#pragma unroll
        for (int j = 0; j < BN / 64; j++) {
            const int row = crow + j * 64;
            cp16(sb + row * 80 + ccol * 16, Bp + (size_t)row * K + k0 + ccol * 8);
        }
    };

    issue(0); CP_COMMIT();
    if (NS > 1) { issue(1); CP_COMMIT(); }

    for (int s = 0; s < NS; s++) {
        if (s + 1 < NS) CP_WAIT1(); else CP_WAIT0();
        __syncthreads();
        if (s + 2 < NS) { issue(s + 2); CP_COMMIT(); }

        const int buf = s % NSTG;
        const uint32_t abase = sbase + buf * STG_HW * 2 + lmoff;
        const uint32_t bbase = abase + SA_STG * 2;

#pragma unroll
        for (int ks = 0; ks < 2; ks++) {
            uint32_t afr[4][4], bfr[NTL][2];
            const uint32_t koff = ks * 32;
#pragma unroll
            for (int mt = 0; mt < 4; mt++) {
                const uint32_t ad = abase + (wm + mt * 16) * 80 + koff;
                LDMX4(afr[mt][0], afr[mt][1], afr[mt][2], afr[mt][3], ad);
            }
#pragma unroll
            for (int np = 0; np < NTL / 2; np++) {
                const uint32_t bd = bbase + (wn + np * 16) * 80 + koff;
                LDMX4(bfr[2 * np][0], bfr[2 * np + 1][0],
                      bfr[2 * np][1], bfr[2 * np + 1][1], bd);
            }
#pragma unroll
            for (int mt = 0; mt < 4; mt++)
#pragma unroll
                for (int nt = 0; nt < NTL; nt++)
                    mma_f16_k16(acc[mt][nt], afr[mt], bfr[nt]);
        }
        __syncthreads();
    }

    const int g = lane >> 2, t = lane & 3;
    if (EPI == 1) {
        __half* C = (__half*)Cv;
#pragma unroll
        for (int mt = 0; mt < 4; mt++) {
            const int row0 = bm + wm + mt * 16 + g;
#pragma unroll
            for (int nt = 0; nt < NTL; nt++) {
                const int col = bn + wn + nt * 8 + 2 * t;
                const float2 e = *(const float2*)&E[col];
                *(__half2*)&C[(size_t)row0 * N + col] =
                    __floats2half2_rn(acc[mt][nt][0] + e.x, acc[mt][nt][1] + e.y);
                *(__half2*)&C[(size_t)(row0 + 8) * N + col] =
                    __floats2half2_rn(acc[mt][nt][2] + e.x, acc[mt][nt][3] + e.y);
            }
        }
    } else if (EPI == 2) {
        float* C = (float*)Cv;
#pragma unroll
        for (int mt = 0; mt < 4; mt++) {
            const int row0 = bm + wm + mt * 16 + g;
#pragma unroll
            for (int nt = 0; nt < NTL; nt++) {
                const int col = bn + wn + nt * 8 + 2 * t;
                const float2 e0 = *(const float2*)&E[(size_t)row0 * N + col];
                const float2 e1 = *(const float2*)&E[(size_t)(row0 + 8) * N + col];
                *(float2*)&C[(size_t)row0 * N + col] =
                    make_float2(acc[mt][nt][0] + e0.x, acc[mt][nt][1] + e0.y);
                *(float2*)&C[(size_t)(row0 + 8) * N + col] =
                    make_float2(acc[mt][nt][2] + e1.x, acc[mt][nt][3] + e1.y);
            }
        }
    } else {
        __half* C = (__half*)Cv;
#pragma unroll
        for (int mt = 0; mt < 4; mt++) {
            const int row0 = bm + wm + mt * 16 + g;
#pragma unroll
            for (int nt = 0; nt < NTL; nt += 2) {
                const int pcol = bn + wn + nt * 8;
                const int ocol = (pcol >> 4) * 8 + 2 * t;
                float v[4];
#pragma unroll
                for (int i = 0; i < 4; i++) {
                    const float gv = acc[mt][nt][i];
                    v[i] = gv / (1.f + __expf(-gv)) * acc[mt][nt + 1][i];
                }
                *(__half2*)&C[(size_t)row0 * IDIM + ocol] = __floats2half2_rn(v[0], v[1]);
                *(__half2*)&C[(size_t)(row0 + 8) * IDIM + ocol] = __floats2half2_rn(v[2], v[3]);
            }
        }
    }
}

// ===========================================================================
// RMSNorm: fp32 in, fp16 out
// ===========================================================================
__global__ __launch_bounds__(256) void rmsnorm_kernel(const float* __restrict__ x,
                                                      const float* __restrict__ w,
                                                      __half* __restrict__ out) {
    const size_t base = (size_t)blockIdx.x * HID;
    const float4* xr = (const float4*)(x + base);
    const float4* w4 = (const float4*)w;
    __half2* orow = (__half2*)(out + base);

    float4 v[4];
    float ss = 0.f;
#pragma unroll
    for (int it = 0; it < 4; it++) {
        v[it] = xr[threadIdx.x + 256 * it];
        ss += v[it].x * v[it].x + v[it].y * v[it].y + v[it].z * v[it].z + v[it].w * v[it].w;
    }
#pragma unroll
    for (int o = 16; o; o >>= 1) ss += __shfl_xor_sync(0xffffffffu, ss, o);

    __shared__ float warpsum[8];
    __shared__ float s_inv;
    const int lane = threadIdx.x & 31, wid = threadIdx.x >> 5;
    if (lane == 0) warpsum[wid] = ss;
    __syncthreads();
    if (threadIdx.x == 0) {
        float tsum = 0.f;
#pragma unroll
        for (int i = 0; i < 8; i++) tsum += warpsum[i];
        s_inv = rsqrtf(tsum * (1.0f / (float)HID) + 1e-6f);
    }
    __syncthreads();
    const float inv = s_inv;
#pragma unroll
    for (int it = 0; it < 4; it++) {
        const int idx = threadIdx.x + 256 * it;
        float4 wv = w4[idx];
        orow[idx * 2 + 0] = __floats2half2_rn(v[it].x * inv * wv.x, v[it].y * inv * wv.y);
        orow[idx * 2 + 1] = __floats2half2_rn(v[it].z * inv * wv.z, v[it].w * inv * wv.w);
    }
}

// ===========================================================================
// RoPE + split (fp16 in): Q,K only (V handled by v_transpose_kernel).
// 256 threads per block: 4 heads x 64 d.
// ===========================================================================
__global__ __launch_bounds__(256) void rope_split_kernel(const __half* __restrict__ qkv,
                                                         const int* __restrict__ positions,
                                                         __half* __restrict__ q,
                                                         __half* __restrict__ k) {
    const int row = blockIdx.x;            // b*S + s
    const int h = blockIdx.y * 4 + (threadIdx.x >> 6);
    const int d = threadIdx.x & 63;        // 0..63
    const int b = row >> 10, s = row & (SEQ - 1);
    const float pos = (float)positions[s];
    const float freq = powf(10000.0f, -(float)d * (1.0f / 64.0f));
    float sn, cs;
    sincosf(pos * freq, &sn, &cs);
    const float scale = 0.08838834764831845f * LOG2E;

    const __half* base = qkv + (size_t)row * (3 * HID) + h * HDIM;
    const float q1 = __half2float(base[d]), q2 = __half2float(base[d + 64]);
    const float k1 = __half2float(base[HID + d]), k2 = __half2float(base[HID + d + 64]);

    const size_t hb = (size_t)(b * NHEAD + h);
    __half* qp = q + (hb * SEQ + s) * HDIM;
    __half* kp = k + (hb * SEQ + s) * HDIM;
    qp[d]      = __float2half_rn((q1 * cs - q2 * sn) * scale);
    qp[d + 64] = __float2half_rn((q2 * cs + q1 * sn) * scale);
    kp[d]      = __float2half_rn(k1 * cs - k2 * sn);
    kp[d + 64] = __float2half_rn(k2 * cs + k1 * sn);
}

// ===========================================================================
// fp16 tensor-core flash attention (causal), log2-domain softmax.
// Heavy q-tiles scheduled first (qt reversed).
// ===========================================================================
#define QPW 68
#define VPW 36
#define AQ_OFF 0
#define AK_OFF (128 * 136)
#define AV_OFF (AK_OFF + 2 * 64 * 136)
#define ATTN_SMEM ((AV_OFF + 2 * 128 * 72) * 2)

__global__ __launch_bounds__(256, 1) void attn_mma_kernel(const __half* __restrict__ q,
                                                          const __half* __restrict__ k,
                                                          const __half* __restrict__ vt,
                                                          __half* __restrict__ attn) {
    extern __shared__ __half asm_[];
    const uint32_t sbase = smem_u32(asm_);
    const int tid = threadIdx.x;
    const int qt = gridDim.x - 1 - blockIdx.x;
    const int h = blockIdx.y, b = blockIdx.z;
    const int w = tid >> 5, lane = tid & 31;
    const int g = lane >> 2, t = lane & 3;

    const size_t hb = (size_t)(b * NHEAD + h);
    const __half* qg = q + (hb * SEQ + qt * 128) * HDIM;
    const __half* kg = k + hb * SEQ * HDIM;
    const __half* vg = vt + hb * HDIM * SEQ;

    {
#pragma unroll
        for (int i = 0; i < 8; i++) {
            const int id = tid + i * 256;
            const int r = id >> 4, c = id & 15;
            cp16(sbase + AQ_OFF * 2 + r * 272 + c * 16, qg + (size_t)r * HDIM + c * 8);
        }
    }
    CP_COMMIT(); CP_WAIT0();
    __syncthreads();

    uint32_t afrQ[8][4];
    {
        const uint32_t* Qw = (const uint32_t*)(asm_ + AQ_OFF);
        const int r0 = 16 * w + g;
#pragma unroll
        for (int ks = 0; ks < 8; ks++) {
            afrQ[ks][0] = Qw[r0 * QPW + ks * 8 + t];
            afrQ[ks][1] = Qw[(r0 + 8) * QPW + ks * 8 + t];
            afrQ[ks][2] = Qw[r0 * QPW + ks * 8 + t + 4];
            afrQ[ks][3] = Qw[(r0 + 8) * QPW + ks * 8 + t + 4];
        }
    }
    __syncthreads();

    float O[16][4];
#pragma unroll
    for (int nt = 0; nt < 16; nt++)
#pragma unroll
        for (int i = 0; i < 4; i++) O[nt][i] = 0.f;
    float m0 = -1e30f, m1 = -1e30f, l0 = 0.f, l1 = 0.f;

    const int NT = 2 * qt + 2;

    auto issue = [&](int j) {
        const uint32_t kb = sbase + AK_OFF * 2 + (j & 1) * (64 * 136 * 2);
        const uint32_t vb = sbase + AV_OFF * 2 + (j & 1) * (128 * 72 * 2);
#pragma unroll
        for (int i = 0; i < 4; i++) {
            const int id = tid + i * 256;
            const int r = id >> 4, c = id & 15;
            cp16(kb + r * 272 + c * 16, kg + (size_t)(j * 64 + r) * HDIM + c * 8);
            const int d = id >> 3, c2 = id & 7;
            cp16(vb + d * 144 + c2 * 16, vg + (size_t)d * SEQ + j * 64 + c2 * 8);
        }
    };

    issue(0); CP_COMMIT();
    if (NT > 1) { issue(1); CP_COMMIT(); }

    const int rowg0 = qt * 128 + 16 * w + g;

    for (int j = 0; j < NT; j++) {
        if (j + 1 < NT) CP_WAIT1(); else CP_WAIT0();
        __syncthreads();

        const uint32_t* Kw = (const uint32_t*)(asm_ + AK_OFF + (j & 1) * 64 * 136);
        const uint32_t* Vw = (const uint32_t*)(asm_ + AV_OFF + (j & 1) * 128 * 72);

        float S[8][4];
#pragma unroll
        for (int nt = 0; nt < 8; nt++)
#pragma unroll
            for (int i = 0; i < 4; i++) S[nt][i] = 0.f;
#pragma unroll
        for (int ks = 0; ks < 8; ks++) {
            uint32_t bf[8][2];
#pragma unroll
            for (int nt = 0; nt < 8; nt++) {
                bf[nt][0] = Kw[(nt * 8 + g) * QPW + ks * 8 + t];
                bf[nt][1] = Kw[(nt * 8 + g) * QPW + ks * 8 + t + 4];
            }
#pragma unroll
            for (int nt = 0; nt < 8; nt++)
                mma_f16_k16(S[nt], afrQ[ks], bf[nt]);
        }

        if (j >= 2 * qt) {
#pragma unroll
            for (int nt = 0; nt < 8; nt++) {
                const int c0 = j * 64 + nt * 8 + 2 * t;
                if (c0 > rowg0)     S[nt][0] = -1e30f;
                if (c0 + 1 > rowg0) S[nt][1] = -1e30f;
                if (c0 > rowg0 + 8)     S[nt][2] = -1e30f;
                if (c0 + 1 > rowg0 + 8) S[nt][3] = -1e30f;
            }
        }

        float mx0 = -1e30f, mx1 = -1e30f;
#pragma unroll
        for (int nt = 0; nt < 8; nt++) {
            mx0 = fmaxf(mx0, fmaxf(S[nt][0], S[nt][1]));
            mx1 = fmaxf(mx1, fmaxf(S[nt][2], S[nt][3]));
        }
        mx0 = fmaxf(mx0, __shfl_xor_sync(0xffffffffu, mx0, 1));
        mx0 = fmaxf(mx0, __shfl_xor_sync(0xffffffffu, mx0, 2));
        mx1 = fmaxf(mx1, __shfl_xor_sync(0xffffffffu, mx1, 1));
        mx1 = fmaxf(mx1, __shfl_xor_sync(0xffffffffu, mx1, 2));
        const float mn0 = fmaxf(m0, mx0), mn1 = fmaxf(m1, mx1);
        const float cr0 = exp2f(m0 - mn0), cr1 = exp2f(m1 - mn1);

        uint32_t pf[4][4];
        float ps0 = 0.f, ps1 = 0.f;
#pragma unroll
        for (int nt = 0; nt < 8; nt++) {
            const uint32_t h01 = ex2h2(S[nt][0] - mn0, S[nt][1] - mn0);
            const uint32_t h23 = ex2h2(S[nt][2] - mn1, S[nt][3] - mn1);
            pf[nt >> 1][(nt & 1) ? 2 : 0] = h01;
            pf[nt >> 1][(nt & 1) ? 3 : 1] = h23;
            const float2 f01 = __half22float2(*(const __half2*)&h01);
            const float2 f23 = __half22float2(*(const __half2*)&h23);
            ps0 += f01.x + f01.y;
            ps1 += f23.x + f23.y;
        }
        ps0 += __shfl_xor_sync(0xffffffffu, ps0, 1);
        ps0 += __shfl_xor_sync(0xffffffffu, ps0, 2);
        ps1 += __shfl_xor_sync(0xffffffffu, ps1, 1);
        ps1 += __shfl_xor_sync(0xffffffffu, ps1, 2);
        l0 = l0 * cr0 + ps0;
        l1 = l1 * cr1 + ps1;
        m0 = mn0; m1 = mn1;
#pragma unroll
        for (int nt = 0; nt < 16; nt++) {
            O[nt][0] *= cr0; O[nt][1] *= cr0;
            O[nt][2] *= cr1; O[nt][3] *= cr1;
        }

#pragma unroll
        for (int kk = 0; kk < 4; kk++) {
#pragma unroll
            for (int nt = 0; nt < 16; nt++) {
                uint32_t bv[2];
                bv[0] = Vw[(nt * 8 + g) * VPW + kk * 8 + t];
                bv[1] = Vw[(nt * 8 + g) * VPW + kk * 8 + t + 4];
                mma_f16_k16(O[nt], pf[kk], bv);
            }
        }

        __syncthreads();
        if (j + 2 < NT) { issue(j + 2); CP_COMMIT(); }
    }

    const float inv0 = 1.0f / l0, inv1 = 1.0f / l1;
    __half* orow0 = attn + ((size_t)(b * SEQ + qt * 128 + 16 * w + g)) * HID + h * HDIM;
    __half* orow1 = orow0 + 8 * HID;
#pragma unroll
    for (int nt = 0; nt < 16; nt++) {
        const int c = nt * 8 + 2 * t;
        *(__half2*)&orow0[c] = __floats2half2_rn(O[nt][0] * inv0, O[nt][1] * inv0);
        *(__half2*)&orow1[c] = __floats2half2_rn(O[nt][2] * inv1, O[nt][3] * inv1);
    }
}

// ===========================================================================
// Launch
// ===========================================================================
extern "C" void kernel_launch(void* const* d_in, const int* in_sizes, int n_in,
                              void* d_out, int out_size) {
    const int*   positions = (const int*)  d_in[0];
    const float* hidden    = (const float*)d_in[1];
    const float* ln1       = (const float*)d_in[2];
    const float* ln2       = (const float*)d_in[3];
    const float* w_qkv     = (const float*)d_in[4];
    const float* b_qkv     = (const float*)d_in[5];
    const float* w_o       = (const float*)d_in[6];
    const float* w_gu      = (const float*)d_in[7];
    const float* w_down    = (const float*)d_in[8];
    float* out = (float*)d_out;

    void* p;
    cudaGetSymbolAddress(&p, g_x);    __half* x    = (__half*)p;
    cudaGetSymbolAddress(&p, g_qkv);  __half* qkv  = (__half*)p;
    cudaGetSymbolAddress(&p, g_q);    __half* qh   = (__half*)p;
    cudaGetSymbolAddress(&p, g_k);    __half* kh   = (__half*)p;
    cudaGetSymbolAddress(&p, g_vt);   __half* vth  = (__half*)p;
    cudaGetSymbolAddress(&p, g_attn); __half* attn = (__half*)p;
    cudaGetSymbolAddress(&p, g_x2);   float*  x2   = (float*)p;
    cudaGetSymbolAddress(&p, g_mlp);  __half* mlp  = (__half*)p;
    cudaGetSymbolAddress(&p, g_wT);   __half* wT   = (__half*)p;
    __half* qkvT = wT + WT_QKV;
    __half* oT   = wT + WT_O;
    __half* guT  = wT + WT_GU;
    __half* dnT  = wT + WT_DN;

    cudaFuncSetAttribute(attn_mma_kernel, cudaFuncAttributeMaxDynamicSharedMemorySize, ATTN_SMEM);
    cudaFuncSetAttribute((const void*)mma_gemm_kernel<1, 8>,
                         cudaFuncAttributeMaxDynamicSharedMemorySize, GEMM_SMEM_N8);
    cudaFuncSetAttribute((const void*)mma_gemm_kernel<3, 8>,
                         cudaFuncAttributeMaxDynamicSharedMemorySize, GEMM_SMEM_N8);
    cudaFuncSetAttribute((const void*)mma_gemm_kernel<2, 4>,
                         cudaFuncAttributeMaxDynamicSharedMemorySize, GEMM_SMEM_N4);

    // ---- fork: weight transposes on s1 ----
    cudaEventRecord(g_ar.evRoot, 0);
    cudaStreamWaitEvent(g_ar.s1, g_ar.evRoot, 0);
    transpose_h_kernel<0><<<dim3((3 * HID) / 32, HID / 32), 256, 0, g_ar.s1>>>(
        w_qkv, qkvT, HID, 3 * HID);
    cudaEventRecord(g_ar.evQ, g_ar.s1);
    transpose_h_kernel<0><<<dim3(HID / 32, HID / 32), 256, 0, g_ar.s1>>>(w_o, oT, HID, HID);
    transpose_h_kernel<1><<<dim3((2 * IDIM) / 32, HID / 32), 256, 0, g_ar.s1>>>(
        w_gu, guT, HID, 2 * IDIM);
    transpose_h_kernel<0><<<dim3(HID / 32, IDIM / 32), 256, 0, g_ar.s1>>>(w_down, dnT, IDIM, HID);
    cudaEventRecord(g_ar.evW, g_ar.s1);

    // ---- main chain on stream 0 ----
    rmsnorm_kernel<<<MROWS, 256>>>(hidden, ln1, x);
    cudaStreamWaitEvent(0, g_ar.evQ, 0);
    // qkv = x @ w_qkv + b_qkv
    if (g_tc.ok)
        tc_gemm_launch(x, qkvT, b_qkv, qkv, MROWS, 3 * HID, HID, 1);
    else
        mma_gemm_kernel<1, 8><<<dim3((3 * HID) / 256, MROWS / GBM), 256, GEMM_SMEM_N8>>>(
            x, qkvT, b_qkv, qkv, MROWS, 3 * HID, HID);
    // rope (Q,K) + coalesced V transpose
    rope_split_kernel<<<dim3(MROWS, NHEAD / 4), 256>>>(qkv, positions, qh, kh);
    v_transpose_kernel<<<dim3(SEQ / 32, HDIM / 32, BZ * NHEAD), 256>>>(qkv, vth);
    attn_mma_kernel<<<dim3(SEQ / 128, NHEAD, BZ), 256, ATTN_SMEM>>>(qh, kh, vth, attn);
    cudaStreamWaitEvent(0, g_ar.evW, 0);
    // x2 = hidden + attn @ w_o
    if (g_tc.ok)
        tc_gemm_launch(attn, oT, hidden, x2, MROWS, HID, HID, 2);
    else
        mma_gemm_kernel<2, 4><<<dim3(HID / 128, MROWS / GBM), 256, GEMM_SMEM_N4>>>(
            attn, oT, hidden, x2, MROWS, HID, HID);
    rmsnorm_kernel<<<MROWS, 256>>>(x2, ln2, x);
    // mlp = silu(gate)*up fused
    if (g_tc.ok)
        tc_gemm_launch(x, guT, nullptr, mlp, MROWS, 2 * IDIM, HID, 3);
    else
        mma_gemm_kernel<3, 8><<<dim3((2 * IDIM) / 256, MROWS / GBM), 256, GEMM_SMEM_N8>>>(
            x, guT, nullptr, mlp, MROWS, 2 * IDIM, HID);
    // out = x2 + mlp @ w_down
    if (g_tc.ok)
        tc_gemm_launch(mlp, dnT, x2, out, MROWS, HID, IDIM, 2);
    else
        mma_gemm_kernel<2, 4><<<dim3(HID / 128, MROWS / GBM), 256, GEMM_SMEM_N4>>>(
            mlp, dnT, x2, out, MROWS, HID, IDIM);
}